// round 1
// baseline (speedup 1.0000x reference)
#include <cuda_runtime.h>
#include <math.h>

#define B_  2
#define T_  2048
#define D_  1024
#define H_  16
#define DH  64
#define M_  (B_*T_)
#define NEG_INF_F (-1.0e9f)

// Scratch (allocation-free rule: __device__ globals)
__device__ float g_q[(size_t)B_*H_*T_*DH];
__device__ float g_k[(size_t)B_*H_*T_*DH];
__device__ float g_v[(size_t)B_*H_*T_*DH];
__device__ float g_attn[(size_t)M_*D_];

// ---------------------------------------------------------------------------
// SGEMM: C = A[M,K] @ W[N,K]^T + bias.  mode 0: C[m*N+n]. mode 1: qkv layout
//   [B,H,T,dh] i.e. C[((b*H+h)*T + t)*DH + d] with b=m/T, t=m%T, h=n/64, d=n%64
// 128x128 tile, BK=8, 256 threads, 8x8 per-thread micro-tile.
// ---------------------------------------------------------------------------
#define GBM 128
#define GBN 128
#define GBK 8
#define GTM 8
#define GTN 8

__global__ __launch_bounds__(256) void sgemm_kernel(
    const float* __restrict__ A, const float* __restrict__ W,
    const float* __restrict__ bias, float* __restrict__ C, int mode)
{
    __shared__ float As[GBK][GBM];
    __shared__ float Bs[GBK][GBN];
    const int K = D_;
    const int N = D_;

    int tid = threadIdx.x;
    int tx = tid & 15;        // 0..15 -> col group
    int ty = tid >> 4;        // 0..15 -> row group
    int m0 = blockIdx.y * GBM;
    int n0 = blockIdx.x * GBN;

    int lrow = tid >> 1;          // 0..127
    int lcol = (tid & 1) * 4;     // 0 or 4
    const float* Aptr = A + (size_t)(m0 + lrow) * K + lcol;
    const float* Wptr = W + (size_t)(n0 + lrow) * K + lcol;

    float acc[GTM][GTN];
#pragma unroll
    for (int i = 0; i < GTM; i++)
#pragma unroll
        for (int j = 0; j < GTN; j++) acc[i][j] = 0.0f;

    for (int k0 = 0; k0 < K; k0 += GBK) {
        float4 av = *(const float4*)(Aptr + k0);
        float4 bv = *(const float4*)(Wptr + k0);
        __syncthreads();
        As[lcol + 0][lrow] = av.x;
        As[lcol + 1][lrow] = av.y;
        As[lcol + 2][lrow] = av.z;
        As[lcol + 3][lrow] = av.w;
        Bs[lcol + 0][lrow] = bv.x;
        Bs[lcol + 1][lrow] = bv.y;
        Bs[lcol + 2][lrow] = bv.z;
        Bs[lcol + 3][lrow] = bv.w;
        __syncthreads();
#pragma unroll
        for (int kk = 0; kk < GBK; kk++) {
            float a[GTM], b[GTN];
#pragma unroll
            for (int i = 0; i < GTM; i++) a[i] = As[kk][ty * GTM + i];
#pragma unroll
            for (int j = 0; j < GTN; j++) b[j] = Bs[kk][tx * GTN + j];
#pragma unroll
            for (int i = 0; i < GTM; i++)
#pragma unroll
                for (int j = 0; j < GTN; j++) acc[i][j] += a[i] * b[j];
        }
    }

    float bb[GTN];
#pragma unroll
    for (int j = 0; j < GTN; j++) bb[j] = __ldg(bias + n0 + tx * GTN + j);

#pragma unroll
    for (int i = 0; i < GTM; i++) {
        int m = m0 + ty * GTM + i;
#pragma unroll
        for (int j = 0; j < GTN; j++) {
            int n = n0 + tx * GTN + j;
            float val = acc[i][j] + bb[j];
            if (mode == 0) {
                C[(size_t)m * N + n] = val;
            } else {
                int b = m >> 11;          // m / T_
                int t = m & (T_ - 1);
                int h = n >> 6;           // n / DH
                int d = n & (DH - 1);
                C[(((size_t)(b * H_ + h)) * T_ + t) * DH + d] = val;
            }
        }
    }
}

// ---------------------------------------------------------------------------
// Flash attention: one thread per query row; BM=128 rows per block.
// K/V tiles of 32x64 fp32 staged in smem (broadcast reads -> conflict-free).
// Online softmax with running max/sum. Output written [B,T,D] row-major.
// ---------------------------------------------------------------------------
#define AT_BN 32

__global__ __launch_bounds__(128) void attn_kernel(
    const float* __restrict__ Q, const float* __restrict__ Kg,
    const float* __restrict__ Vg, const int* __restrict__ mask,
    float* __restrict__ O)
{
    __shared__ float Ks[AT_BN][DH];
    __shared__ float Vs[AT_BN][DH];
    __shared__ int   Msk[AT_BN];

    int bh = blockIdx.y;         // 0..B_*H_-1
    int b  = bh >> 4;            // bh / H_
    int h  = bh & (H_ - 1);
    int row = blockIdx.x * 128 + threadIdx.x;   // query t within sequence

    const float* qptr = Q + ((size_t)bh * T_ + row) * DH;
    float q[DH];
#pragma unroll
    for (int i = 0; i < DH / 4; i++) {
        float4 v4 = *(const float4*)(qptr + i * 4);
        q[i * 4 + 0] = v4.x; q[i * 4 + 1] = v4.y;
        q[i * 4 + 2] = v4.z; q[i * 4 + 3] = v4.w;
    }

    float o[DH];
#pragma unroll
    for (int d = 0; d < DH; d++) o[d] = 0.0f;
    float mmax = -INFINITY;
    float l = 0.0f;

    const float* kbase0 = Kg + (size_t)bh * T_ * DH;
    const float* vbase0 = Vg + (size_t)bh * T_ * DH;

    for (int n0 = 0; n0 < T_; n0 += AT_BN) {
        __syncthreads();
        // cooperative tile load: 32*64 floats each = 512 float4s, 128 threads
        const float* kbase = kbase0 + (size_t)n0 * DH;
        const float* vbase = vbase0 + (size_t)n0 * DH;
#pragma unroll
        for (int i = 0; i < 4; i++) {
            int e = (threadIdx.x + i * 128) * 4;
            *(float4*)(&Ks[0][0] + e) = *(const float4*)(kbase + e);
            *(float4*)(&Vs[0][0] + e) = *(const float4*)(vbase + e);
        }
        if (threadIdx.x < AT_BN)
            Msk[threadIdx.x] = mask[b * T_ + n0 + threadIdx.x];
        __syncthreads();

        float s[AT_BN];
#pragma unroll
        for (int j = 0; j < AT_BN; j++) {
            float accs = 0.0f;
#pragma unroll
            for (int d = 0; d < DH; d += 4) {
                float4 kv = *(const float4*)(&Ks[j][d]);
                accs += q[d + 0] * kv.x;
                accs += q[d + 1] * kv.y;
                accs += q[d + 2] * kv.z;
                accs += q[d + 3] * kv.w;
            }
            s[j] = (Msk[j] != 0) ? accs * 0.125f : NEG_INF_F;
        }

        float tmax = s[0];
#pragma unroll
        for (int j = 1; j < AT_BN; j++) tmax = fmaxf(tmax, s[j]);
        float mnew = fmaxf(mmax, tmax);
        float corr = __expf(mmax - mnew);
        l *= corr;
#pragma unroll
        for (int d = 0; d < DH; d++) o[d] *= corr;

#pragma unroll
        for (int j = 0; j < AT_BN; j++) {
            float p = __expf(s[j] - mnew);
            l += p;
#pragma unroll
            for (int d = 0; d < DH; d += 4) {
                float4 vv = *(const float4*)(&Vs[j][d]);
                o[d + 0] += p * vv.x;
                o[d + 1] += p * vv.y;
                o[d + 2] += p * vv.z;
                o[d + 3] += p * vv.w;
            }
        }
        mmax = mnew;
    }

    float inv = 1.0f / l;
    float* optr = O + ((size_t)(b * T_ + row)) * D_ + h * DH;
#pragma unroll
    for (int d = 0; d < DH; d += 4) {
        float4 v4;
        v4.x = o[d + 0] * inv; v4.y = o[d + 1] * inv;
        v4.z = o[d + 2] * inv; v4.w = o[d + 3] * inv;
        *(float4*)(optr + d) = v4;
    }
}

// ---------------------------------------------------------------------------
extern "C" void kernel_launch(void* const* d_in, const int* in_sizes, int n_in,
                              void* d_out, int out_size)
{
    (void)in_sizes; (void)n_in; (void)out_size;
    const float* x    = (const float*)d_in[0];
    const int*   mask = (const int*)  d_in[1];
    const float* Wq   = (const float*)d_in[2];
    const float* bq   = (const float*)d_in[3];
    const float* Wk   = (const float*)d_in[4];
    const float* bk   = (const float*)d_in[5];
    const float* Wv   = (const float*)d_in[6];
    const float* bv   = (const float*)d_in[7];
    const float* Wo   = (const float*)d_in[8];
    const float* bo   = (const float*)d_in[9];
    float* out = (float*)d_out;

    float *q, *k, *v, *attn;
    cudaGetSymbolAddress((void**)&q,    g_q);
    cudaGetSymbolAddress((void**)&k,    g_k);
    cudaGetSymbolAddress((void**)&v,    g_v);
    cudaGetSymbolAddress((void**)&attn, g_attn);

    dim3 gg(D_ / GBN, M_ / GBM);   // (8, 32)
    sgemm_kernel<<<gg, 256>>>(x, Wq, bq, q, 1);
    sgemm_kernel<<<gg, 256>>>(x, Wk, bk, k, 1);
    sgemm_kernel<<<gg, 256>>>(x, Wv, bv, v, 1);

    attn_kernel<<<dim3(T_ / 128, B_ * H_), 128>>>(q, k, v, mask, attn);

    sgemm_kernel<<<gg, 256>>>(attn, Wo, bo, out, 0);
}

// round 2
// speedup vs baseline: 1.3753x; 1.3753x over previous
#include <cuda_runtime.h>
#include <math.h>

#define B_  2
#define T_  2048
#define D_  1024
#define H_  16
#define DH  64
#define M_  (B_*T_)
#define NEG_INF_F (-1.0e9f)

// Scratch (allocation-free rule: __device__ globals)
__device__ float g_q[(size_t)B_*H_*T_*DH];
__device__ float g_k[(size_t)B_*H_*T_*DH];
__device__ float g_v[(size_t)B_*H_*T_*DH];
__device__ float g_attn[(size_t)M_*D_];

// ===========================================================================
// tf32 helpers
// ===========================================================================
__device__ __forceinline__ unsigned f2tf32(float x) {
    unsigned r;
    asm("cvt.rna.tf32.f32 %0, %1;" : "=r"(r) : "f"(x));
    return r;
}

__device__ __forceinline__ void mma_tf32(float* c, const unsigned* a, const unsigned* b) {
    asm volatile(
        "mma.sync.aligned.m16n8k8.row.col.f32.tf32.tf32.f32 "
        "{%0,%1,%2,%3}, {%4,%5,%6,%7}, {%8,%9}, {%0,%1,%2,%3};\n"
        : "+f"(c[0]), "+f"(c[1]), "+f"(c[2]), "+f"(c[3])
        : "r"(a[0]), "r"(a[1]), "r"(a[2]), "r"(a[3]),
          "r"(b[0]), "r"(b[1]));
}

// ===========================================================================
// Tensor-core GEMM: C = A[M,1024] @ W[1024,1024]^T + bias
// Block tile 128x128, K-tile 32. 8 warps in 2x4 grid, 64x32 warp tile.
// Smem row-major [row][36] pad -> fragment LDS banks = 4*g + l (conflict-free)
// mode 0: C[m*1024+n];  mode 1: qkv layout [B,H,T,dh]
// blockIdx.z picks (W,bias,C) set 0..2 (QKV fused in one launch).
// ===========================================================================
#define SKA 36

__device__ __forceinline__ void store_out(float* C, int mode, int m, int n,
                                          float v0, float v1) {
    if (mode == 0) {
        float2 v; v.x = v0; v.y = v1;
        *(float2*)(C + (size_t)m * D_ + n) = v;
    } else {
        int b = m >> 11;          // m / T_
        int t = m & (T_ - 1);
        int h = n >> 6;           // n / DH
        int d = n & (DH - 1);
        float2 v; v.x = v0; v.y = v1;
        *(float2*)(C + (((size_t)(b * H_ + h)) * T_ + t) * DH + d) = v;
    }
}

__global__ __launch_bounds__(256) void mma_gemm(
    const float* __restrict__ A,
    const float* __restrict__ W0, const float* __restrict__ bb0, float* __restrict__ C0,
    const float* __restrict__ W1, const float* __restrict__ bb1, float* __restrict__ C1,
    const float* __restrict__ W2, const float* __restrict__ bb2, float* __restrict__ C2,
    int mode)
{
    const int z = blockIdx.z;
    const float* W    = (z == 0) ? W0  : (z == 1) ? W1  : W2;
    const float* bias = (z == 0) ? bb0 : (z == 1) ? bb1 : bb2;
    float* C          = (z == 0) ? C0  : (z == 1) ? C1  : C2;

    __shared__ unsigned As[128][SKA];
    __shared__ unsigned Ws[128][SKA];

    const int tid  = threadIdx.x;
    const int warp = tid >> 5, lane = tid & 31;
    const int g = lane >> 2, l = lane & 3;
    const int wm = (warp >> 2) * 64;    // warp m offset (0/64)
    const int wn = (warp & 3) * 32;     // warp n offset (0..96)
    const int m0 = blockIdx.y * 128;
    const int n0 = blockIdx.x * 128;

    // global staging mapping: float4 q = tid + j*256 -> row q>>3, col (q&7)*4
    const int lm = tid >> 3;            // 0..31 base row; rows lm + j*32
    const int lc = (tid & 7) * 4;       // col within K-tile

    float acc[4][4][4];
#pragma unroll
    for (int mi = 0; mi < 4; mi++)
#pragma unroll
        for (int ni = 0; ni < 4; ni++)
#pragma unroll
            for (int e = 0; e < 4; e++) acc[mi][ni][e] = 0.0f;

    float4 stA[4], stW[4];
    // prologue: load K-tile 0
#pragma unroll
    for (int j = 0; j < 4; j++) {
        int row = lm + j * 32;
        stA[j] = *(const float4*)(A + (size_t)(m0 + row) * D_ + lc);
        stW[j] = *(const float4*)(W + (size_t)(n0 + row) * D_ + lc);
    }
#pragma unroll
    for (int j = 0; j < 4; j++) {
        int row = lm + j * 32;
        As[row][lc + 0] = f2tf32(stA[j].x);
        As[row][lc + 1] = f2tf32(stA[j].y);
        As[row][lc + 2] = f2tf32(stA[j].z);
        As[row][lc + 3] = f2tf32(stA[j].w);
        Ws[row][lc + 0] = f2tf32(stW[j].x);
        Ws[row][lc + 1] = f2tf32(stW[j].y);
        Ws[row][lc + 2] = f2tf32(stW[j].z);
        Ws[row][lc + 3] = f2tf32(stW[j].w);
    }
    __syncthreads();

    for (int kt = 0; kt < 32; kt++) {
        const bool has_next = (kt < 31);
        if (has_next) {
            const int kg = (kt + 1) * 32 + lc;
#pragma unroll
            for (int j = 0; j < 4; j++) {
                int row = lm + j * 32;
                stA[j] = *(const float4*)(A + (size_t)(m0 + row) * D_ + kg);
                stW[j] = *(const float4*)(W + (size_t)(n0 + row) * D_ + kg);
            }
        }

        // compute 4 k-steps of 8 from smem
#pragma unroll
        for (int kk = 0; kk < 4; kk++) {
            const int kb = kk * 8;
            unsigned af[4][4];
#pragma unroll
            for (int mi = 0; mi < 4; mi++) {
                int r = wm + mi * 16 + g;
                af[mi][0] = As[r][kb + l];
                af[mi][1] = As[r + 8][kb + l];
                af[mi][2] = As[r][kb + l + 4];
                af[mi][3] = As[r + 8][kb + l + 4];
            }
            unsigned bf[4][2];
#pragma unroll
            for (int ni = 0; ni < 4; ni++) {
                int cN = wn + ni * 8 + g;
                bf[ni][0] = Ws[cN][kb + l];
                bf[ni][1] = Ws[cN][kb + l + 4];
            }
#pragma unroll
            for (int mi = 0; mi < 4; mi++)
#pragma unroll
                for (int ni = 0; ni < 4; ni++)
                    mma_tf32(acc[mi][ni], af[mi], bf[ni]);
        }

        if (has_next) {
            __syncthreads();
#pragma unroll
            for (int j = 0; j < 4; j++) {
                int row = lm + j * 32;
                As[row][lc + 0] = f2tf32(stA[j].x);
                As[row][lc + 1] = f2tf32(stA[j].y);
                As[row][lc + 2] = f2tf32(stA[j].z);
                As[row][lc + 3] = f2tf32(stA[j].w);
                Ws[row][lc + 0] = f2tf32(stW[j].x);
                Ws[row][lc + 1] = f2tf32(stW[j].y);
                Ws[row][lc + 2] = f2tf32(stW[j].z);
                Ws[row][lc + 3] = f2tf32(stW[j].w);
            }
            __syncthreads();
        }
    }

    // epilogue
#pragma unroll
    for (int ni = 0; ni < 4; ni++) {
        int n = n0 + wn + ni * 8 + 2 * l;
        float bv0 = __ldg(bias + n);
        float bv1 = __ldg(bias + n + 1);
#pragma unroll
        for (int mi = 0; mi < 4; mi++) {
            int m = m0 + wm + mi * 16 + g;
            store_out(C, mode, m,     n, acc[mi][ni][0] + bv0, acc[mi][ni][1] + bv1);
            store_out(C, mode, m + 8, n, acc[mi][ni][2] + bv0, acc[mi][ni][3] + bv1);
        }
    }
}

// ===========================================================================
// Flash attention: thread PAIR per query row (each owns dh/2 = 32).
// 256 threads = 128 rows per block. K/V tiles 32x64 staged in smem with the
// two 32-float halves padded 36 floats apart (conflict-free 2-addr broadcast).
// QK dot combined via shfl_xor(1). Scores chunked 16 to cap registers.
// ===========================================================================
#define AT_BN 32
#define KROW  72    // halves at float offsets 0 and 36

__global__ __launch_bounds__(256, 2) void attn_kernel(
    const float* __restrict__ Q, const float* __restrict__ Kg,
    const float* __restrict__ Vg, const int* __restrict__ mask,
    float* __restrict__ O)
{
    __shared__ float Ks[AT_BN][KROW];
    __shared__ float Vs[AT_BN][KROW];
    __shared__ int   Msk[AT_BN];

    const int bh = blockIdx.y;
    const int b  = bh >> 4;
    const int h  = bh & (H_ - 1);
    const int tid = threadIdx.x;
    const int r = tid >> 1;            // row within block
    const int p = tid & 1;             // dh half
    const int row  = blockIdx.x * 128 + r;
    const int hoff = p * 32;           // global dh offset
    const int soff = p * 36;           // smem half offset

    const float* qptr = Q + ((size_t)bh * T_ + row) * DH + hoff;
    float q[32];
#pragma unroll
    for (int i = 0; i < 8; i++) {
        float4 v4 = *(const float4*)(qptr + i * 4);
        q[i*4+0] = v4.x; q[i*4+1] = v4.y; q[i*4+2] = v4.z; q[i*4+3] = v4.w;
    }

    float o[32];
#pragma unroll
    for (int d = 0; d < 32; d++) o[d] = 0.0f;
    float mmax = -INFINITY;
    float l = 0.0f;

    const float* kbase0 = Kg + (size_t)bh * T_ * DH;
    const float* vbase0 = Vg + (size_t)bh * T_ * DH;

    for (int n0 = 0; n0 < T_; n0 += AT_BN) {
        __syncthreads();
        const float* kbase = kbase0 + (size_t)n0 * DH;
        const float* vbase = vbase0 + (size_t)n0 * DH;
#pragma unroll
        for (int i = 0; i < 2; i++) {
            int idx = tid + i * 256;           // 512 float4 per array
            int j = idx >> 4, c = idx & 15;
            int dst = j * KROW + (c < 8 ? c * 4 : 36 + (c - 8) * 4);
            int src = j * 64 + c * 4;
            *(float4*)(&Ks[0][0] + dst) = *(const float4*)(kbase + src);
            *(float4*)(&Vs[0][0] + dst) = *(const float4*)(vbase + src);
        }
        if (tid < AT_BN) Msk[tid] = mask[b * T_ + n0 + tid];
        __syncthreads();

#pragma unroll
        for (int ch = 0; ch < 2; ch++) {
            float s[16];
#pragma unroll
            for (int j = 0; j < 16; j++) {
                const int jj = ch * 16 + j;
                const float* kr = &Ks[jj][soff];
                float accs = 0.0f;
#pragma unroll
                for (int d4 = 0; d4 < 8; d4++) {
                    float4 kv = *(const float4*)(kr + d4 * 4);
                    accs += q[d4*4+0] * kv.x;
                    accs += q[d4*4+1] * kv.y;
                    accs += q[d4*4+2] * kv.z;
                    accs += q[d4*4+3] * kv.w;
                }
                accs += __shfl_xor_sync(0xffffffffu, accs, 1);
                s[j] = (Msk[jj] != 0) ? accs * 0.125f : NEG_INF_F;
            }
            float tmax = s[0];
#pragma unroll
            for (int j = 1; j < 16; j++) tmax = fmaxf(tmax, s[j]);
            float mnew = fmaxf(mmax, tmax);
            float corr = __expf(mmax - mnew);
            l *= corr;
#pragma unroll
            for (int d = 0; d < 32; d++) o[d] *= corr;
#pragma unroll
            for (int j = 0; j < 16; j++) {
                float pw = __expf(s[j] - mnew);
                l += pw;
                const float* vr = &Vs[ch * 16 + j][soff];
#pragma unroll
                for (int d4 = 0; d4 < 8; d4++) {
                    float4 vv = *(const float4*)(vr + d4 * 4);
                    o[d4*4+0] += pw * vv.x;
                    o[d4*4+1] += pw * vv.y;
                    o[d4*4+2] += pw * vv.z;
                    o[d4*4+3] += pw * vv.w;
                }
            }
            mmax = mnew;
        }
    }

    const float inv = 1.0f / l;
    float* optr = O + ((size_t)(b * T_ + row)) * D_ + h * DH + hoff;
#pragma unroll
    for (int d4 = 0; d4 < 8; d4++) {
        float4 v4;
        v4.x = o[d4*4+0] * inv; v4.y = o[d4*4+1] * inv;
        v4.z = o[d4*4+2] * inv; v4.w = o[d4*4+3] * inv;
        *(float4*)(optr + d4 * 4) = v4;
    }
}

// ===========================================================================
extern "C" void kernel_launch(void* const* d_in, const int* in_sizes, int n_in,
                              void* d_out, int out_size)
{
    (void)in_sizes; (void)n_in; (void)out_size;
    const float* x    = (const float*)d_in[0];
    const int*   mask = (const int*)  d_in[1];
    const float* Wq   = (const float*)d_in[2];
    const float* bq   = (const float*)d_in[3];
    const float* Wk   = (const float*)d_in[4];
    const float* bk   = (const float*)d_in[5];
    const float* Wv   = (const float*)d_in[6];
    const float* bv   = (const float*)d_in[7];
    const float* Wo   = (const float*)d_in[8];
    const float* bo   = (const float*)d_in[9];
    float* out = (float*)d_out;

    float *q, *k, *v, *attn;
    cudaGetSymbolAddress((void**)&q,    g_q);
    cudaGetSymbolAddress((void**)&k,    g_k);
    cudaGetSymbolAddress((void**)&v,    g_v);
    cudaGetSymbolAddress((void**)&attn, g_attn);

    // fused QKV projections: blockIdx.z selects weight set
    mma_gemm<<<dim3(D_/128, M_/128, 3), 256>>>(
        x, Wq, bq, q, Wk, bk, k, Wv, bv, v, 1);

    attn_kernel<<<dim3(T_/128, B_*H_), 256>>>(q, k, v, mask, attn);

    // output projection
    mma_gemm<<<dim3(D_/128, M_/128, 1), 256>>>(
        attn, Wo, bo, out, Wo, bo, out, Wo, bo, out, 0);
}

// round 3
// speedup vs baseline: 3.2553x; 2.3670x over previous
#include <cuda_runtime.h>
#include <cuda_fp16.h>
#include <math.h>

#define B_  2
#define T_  2048
#define D_  1024
#define H_  16
#define DH  64
#define M_  (B_*T_)
#define NEG_INF_F (-1.0e9f)

// Scratch (allocation-free rule: __device__ globals)
__device__ float g_q[(size_t)B_*H_*T_*DH];
__device__ float g_k[(size_t)B_*H_*T_*DH];
__device__ float g_v[(size_t)B_*H_*T_*DH];
__device__ float g_attn[(size_t)M_*D_];

// ===========================================================================
// mma helpers
// ===========================================================================
__device__ __forceinline__ unsigned f2tf32(float x) {
    unsigned r;
    asm("cvt.rna.tf32.f32 %0, %1;" : "=r"(r) : "f"(x));
    return r;
}

__device__ __forceinline__ void mma_tf32(float* c, const unsigned* a, const unsigned* b) {
    asm volatile(
        "mma.sync.aligned.m16n8k8.row.col.f32.tf32.tf32.f32 "
        "{%0,%1,%2,%3}, {%4,%5,%6,%7}, {%8,%9}, {%0,%1,%2,%3};\n"
        : "+f"(c[0]), "+f"(c[1]), "+f"(c[2]), "+f"(c[3])
        : "r"(a[0]), "r"(a[1]), "r"(a[2]), "r"(a[3]),
          "r"(b[0]), "r"(b[1]));
}

__device__ __forceinline__ void mma_f16(float* c, const unsigned* a, const unsigned* b) {
    asm volatile(
        "mma.sync.aligned.m16n8k16.row.col.f32.f16.f16.f32 "
        "{%0,%1,%2,%3}, {%4,%5,%6,%7}, {%8,%9}, {%0,%1,%2,%3};\n"
        : "+f"(c[0]), "+f"(c[1]), "+f"(c[2]), "+f"(c[3])
        : "r"(a[0]), "r"(a[1]), "r"(a[2]), "r"(a[3]),
          "r"(b[0]), "r"(b[1]));
}

__device__ __forceinline__ unsigned packh2(float lo, float hi) {
    __half2 h = __floats2half2_rn(lo, hi);
    return *(unsigned*)&h;
}

// ===========================================================================
// Tensor-core GEMM (tf32): C = A[M,1024] @ W[1024,1024]^T + bias
// (unchanged from round 2)
// ===========================================================================
#define SKA 36

__device__ __forceinline__ void store_out(float* C, int mode, int m, int n,
                                          float v0, float v1) {
    if (mode == 0) {
        float2 v; v.x = v0; v.y = v1;
        *(float2*)(C + (size_t)m * D_ + n) = v;
    } else {
        int b = m >> 11;
        int t = m & (T_ - 1);
        int h = n >> 6;
        int d = n & (DH - 1);
        float2 v; v.x = v0; v.y = v1;
        *(float2*)(C + (((size_t)(b * H_ + h)) * T_ + t) * DH + d) = v;
    }
}

__global__ __launch_bounds__(256) void mma_gemm(
    const float* __restrict__ A,
    const float* __restrict__ W0, const float* __restrict__ bb0, float* __restrict__ C0,
    const float* __restrict__ W1, const float* __restrict__ bb1, float* __restrict__ C1,
    const float* __restrict__ W2, const float* __restrict__ bb2, float* __restrict__ C2,
    int mode)
{
    const int z = blockIdx.z;
    const float* W    = (z == 0) ? W0  : (z == 1) ? W1  : W2;
    const float* bias = (z == 0) ? bb0 : (z == 1) ? bb1 : bb2;
    float* C          = (z == 0) ? C0  : (z == 1) ? C1  : C2;

    __shared__ unsigned As[128][SKA];
    __shared__ unsigned Ws[128][SKA];

    const int tid  = threadIdx.x;
    const int warp = tid >> 5, lane = tid & 31;
    const int g = lane >> 2, l = lane & 3;
    const int wm = (warp >> 2) * 64;
    const int wn = (warp & 3) * 32;
    const int m0 = blockIdx.y * 128;
    const int n0 = blockIdx.x * 128;

    const int lm = tid >> 3;
    const int lc = (tid & 7) * 4;

    float acc[4][4][4];
#pragma unroll
    for (int mi = 0; mi < 4; mi++)
#pragma unroll
        for (int ni = 0; ni < 4; ni++)
#pragma unroll
            for (int e = 0; e < 4; e++) acc[mi][ni][e] = 0.0f;

    float4 stA[4], stW[4];
#pragma unroll
    for (int j = 0; j < 4; j++) {
        int row = lm + j * 32;
        stA[j] = *(const float4*)(A + (size_t)(m0 + row) * D_ + lc);
        stW[j] = *(const float4*)(W + (size_t)(n0 + row) * D_ + lc);
    }
#pragma unroll
    for (int j = 0; j < 4; j++) {
        int row = lm + j * 32;
        As[row][lc + 0] = f2tf32(stA[j].x);
        As[row][lc + 1] = f2tf32(stA[j].y);
        As[row][lc + 2] = f2tf32(stA[j].z);
        As[row][lc + 3] = f2tf32(stA[j].w);
        Ws[row][lc + 0] = f2tf32(stW[j].x);
        Ws[row][lc + 1] = f2tf32(stW[j].y);
        Ws[row][lc + 2] = f2tf32(stW[j].z);
        Ws[row][lc + 3] = f2tf32(stW[j].w);
    }
    __syncthreads();

    for (int kt = 0; kt < 32; kt++) {
        const bool has_next = (kt < 31);
        if (has_next) {
            const int kg = (kt + 1) * 32 + lc;
#pragma unroll
            for (int j = 0; j < 4; j++) {
                int row = lm + j * 32;
                stA[j] = *(const float4*)(A + (size_t)(m0 + row) * D_ + kg);
                stW[j] = *(const float4*)(W + (size_t)(n0 + row) * D_ + kg);
            }
        }

#pragma unroll
        for (int kk = 0; kk < 4; kk++) {
            const int kb = kk * 8;
            unsigned af[4][4];
#pragma unroll
            for (int mi = 0; mi < 4; mi++) {
                int r = wm + mi * 16 + g;
                af[mi][0] = As[r][kb + l];
                af[mi][1] = As[r + 8][kb + l];
                af[mi][2] = As[r][kb + l + 4];
                af[mi][3] = As[r + 8][kb + l + 4];
            }
            unsigned bf[4][2];
#pragma unroll
            for (int ni = 0; ni < 4; ni++) {
                int cN = wn + ni * 8 + g;
                bf[ni][0] = Ws[cN][kb + l];
                bf[ni][1] = Ws[cN][kb + l + 4];
            }
#pragma unroll
            for (int mi = 0; mi < 4; mi++)
#pragma unroll
                for (int ni = 0; ni < 4; ni++)
                    mma_tf32(acc[mi][ni], af[mi], bf[ni]);
        }

        if (has_next) {
            __syncthreads();
#pragma unroll
            for (int j = 0; j < 4; j++) {
                int row = lm + j * 32;
                As[row][lc + 0] = f2tf32(stA[j].x);
                As[row][lc + 1] = f2tf32(stA[j].y);
                As[row][lc + 2] = f2tf32(stA[j].z);
                As[row][lc + 3] = f2tf32(stA[j].w);
                Ws[row][lc + 0] = f2tf32(stW[j].x);
                Ws[row][lc + 1] = f2tf32(stW[j].y);
                Ws[row][lc + 2] = f2tf32(stW[j].z);
                Ws[row][lc + 3] = f2tf32(stW[j].w);
            }
            __syncthreads();
        }
    }

#pragma unroll
    for (int ni = 0; ni < 4; ni++) {
        int n = n0 + wn + ni * 8 + 2 * l;
        float bv0 = __ldg(bias + n);
        float bv1 = __ldg(bias + n + 1);
#pragma unroll
        for (int mi = 0; mi < 4; mi++) {
            int m = m0 + wm + mi * 16 + g;
            store_out(C, mode, m,     n, acc[mi][ni][0] + bv0, acc[mi][ni][1] + bv1);
            store_out(C, mode, m + 8, n, acc[mi][ni][2] + bv0, acc[mi][ni][3] + bv1);
        }
    }
}

// ===========================================================================
// Flash attention with fp16 tensor cores (FA2 layout).
// BM=64 (4 warps x m16), BN=64, dh=64. fp32 accumulate + online softmax.
// K in smem [t][72] fp16 (S b-frags contiguous half2, conflict-free).
// V in smem TRANSPOSED [d][72] fp16 (PV b-frags contiguous half2).
// S accumulator regs pack directly into P A-operand fragments (no shuffles).
// ===========================================================================
#define FBM 64
#define FBN 64
#define KLD 72

__global__ __launch_bounds__(128) void attn_mma_kernel(
    const float* __restrict__ Q, const float* __restrict__ Kg,
    const float* __restrict__ Vg, const int* __restrict__ mask,
    float* __restrict__ O)
{
    __shared__ __half Ks[FBN][KLD];
    __shared__ __half Vt[DH][KLD];
    __shared__ int    Msk[FBN];

    const int bh = blockIdx.y;
    const int b  = bh >> 4;
    const int h  = bh & (H_ - 1);
    const int tid  = threadIdx.x;
    const int warp = tid >> 5, lane = tid & 31;
    const int g = lane >> 2, l = lane & 3;
    const int mrow0 = blockIdx.x * FBM + warp * 16;

    // Q fragments for the whole row-block: 4 k16-tiles x 4 regs, kept in regs.
    unsigned qf[4][4];
    {
        const float* qb = Q + ((size_t)bh * T_ + mrow0) * DH;
#pragma unroll
        for (int kt = 0; kt < 4; kt++) {
            float2 x0 = *(const float2*)(qb + (size_t)g       * DH + kt*16 + 2*l);
            float2 x1 = *(const float2*)(qb + (size_t)(g + 8) * DH + kt*16 + 2*l);
            float2 x2 = *(const float2*)(qb + (size_t)g       * DH + kt*16 + 2*l + 8);
            float2 x3 = *(const float2*)(qb + (size_t)(g + 8) * DH + kt*16 + 2*l + 8);
            qf[kt][0] = packh2(x0.x, x0.y);
            qf[kt][1] = packh2(x1.x, x1.y);
            qf[kt][2] = packh2(x2.x, x2.y);
            qf[kt][3] = packh2(x3.x, x3.y);
        }
    }

    float oa[8][4];
#pragma unroll
    for (int ni = 0; ni < 8; ni++)
#pragma unroll
        for (int e = 0; e < 4; e++) oa[ni][e] = 0.0f;
    float m0 = -INFINITY, m1 = -INFINITY;
    float l0 = 0.0f, l1 = 0.0f;

    const float* kb0 = Kg + (size_t)bh * T_ * DH;
    const float* vb0 = Vg + (size_t)bh * T_ * DH;

    for (int n0 = 0; n0 < T_; n0 += FBN) {
        __syncthreads();
        // cooperative K (fp16) + V (fp16, transposed) tile load
#pragma unroll
        for (int i = 0; i < 8; i++) {
            int idx = tid + i * 128;          // 1024 float4 per tensor
            int row = idx >> 4;
            int c4  = (idx & 15) * 4;
            float4 kv = *(const float4*)(kb0 + (size_t)(n0 + row) * DH + c4);
            uint2 u;
            u.x = packh2(kv.x, kv.y);
            u.y = packh2(kv.z, kv.w);
            *(uint2*)&Ks[row][c4] = u;
            float4 vv = *(const float4*)(vb0 + (size_t)(n0 + row) * DH + c4);
            Vt[c4 + 0][row] = __float2half_rn(vv.x);
            Vt[c4 + 1][row] = __float2half_rn(vv.y);
            Vt[c4 + 2][row] = __float2half_rn(vv.z);
            Vt[c4 + 3][row] = __float2half_rn(vv.w);
        }
        if (tid < FBN) Msk[tid] = mask[b * T_ + n0 + tid];
        __syncthreads();

        // S = Q K^T (fp32 accum)
        float sa[8][4];
#pragma unroll
        for (int ni = 0; ni < 8; ni++)
#pragma unroll
            for (int e = 0; e < 4; e++) sa[ni][e] = 0.0f;
#pragma unroll
        for (int kt = 0; kt < 4; kt++) {
#pragma unroll
            for (int ni = 0; ni < 8; ni++) {
                unsigned bq[2];
                bq[0] = *(const unsigned*)&Ks[ni*8 + g][kt*16 + 2*l];
                bq[1] = *(const unsigned*)&Ks[ni*8 + g][kt*16 + 2*l + 8];
                mma_f16(sa[ni], qf[kt], bq);
            }
        }

        // scale + mask
#pragma unroll
        for (int ni = 0; ni < 8; ni++) {
            int c0m = Msk[ni*8 + 2*l];
            int c1m = Msk[ni*8 + 2*l + 1];
            sa[ni][0] = c0m ? sa[ni][0] * 0.125f : NEG_INF_F;
            sa[ni][1] = c1m ? sa[ni][1] * 0.125f : NEG_INF_F;
            sa[ni][2] = c0m ? sa[ni][2] * 0.125f : NEG_INF_F;
            sa[ni][3] = c1m ? sa[ni][3] * 0.125f : NEG_INF_F;
        }

        // row max across 8 tiles then across the lane quad
        float rm0 = -INFINITY, rm1 = -INFINITY;
#pragma unroll
        for (int ni = 0; ni < 8; ni++) {
            rm0 = fmaxf(rm0, fmaxf(sa[ni][0], sa[ni][1]));
            rm1 = fmaxf(rm1, fmaxf(sa[ni][2], sa[ni][3]));
        }
        rm0 = fmaxf(rm0, __shfl_xor_sync(0xffffffffu, rm0, 1));
        rm0 = fmaxf(rm0, __shfl_xor_sync(0xffffffffu, rm0, 2));
        rm1 = fmaxf(rm1, __shfl_xor_sync(0xffffffffu, rm1, 1));
        rm1 = fmaxf(rm1, __shfl_xor_sync(0xffffffffu, rm1, 2));
        float mn0 = fmaxf(m0, rm0);
        float mn1 = fmaxf(m1, rm1);
        float cr0 = __expf(m0 - mn0);
        float cr1 = __expf(m1 - mn1);

        // exp, pack P, partial row sums
        unsigned pk[8][2];
        float ts0 = 0.0f, ts1 = 0.0f;
#pragma unroll
        for (int ni = 0; ni < 8; ni++) {
            float e0 = __expf(sa[ni][0] - mn0);
            float e1 = __expf(sa[ni][1] - mn0);
            float e2 = __expf(sa[ni][2] - mn1);
            float e3 = __expf(sa[ni][3] - mn1);
            ts0 += e0 + e1;
            ts1 += e2 + e3;
            pk[ni][0] = packh2(e0, e1);
            pk[ni][1] = packh2(e2, e3);
        }
        l0 = l0 * cr0 + ts0;
        l1 = l1 * cr1 + ts1;
#pragma unroll
        for (int ni = 0; ni < 8; ni++) {
            oa[ni][0] *= cr0; oa[ni][1] *= cr0;
            oa[ni][2] *= cr1; oa[ni][3] *= cr1;
        }
        m0 = mn0; m1 = mn1;

        // O += P V  (P A-frags = packed S accumulators; V^T b-frags from smem)
#pragma unroll
        for (int kt2 = 0; kt2 < 4; kt2++) {
            unsigned pa[4];
            pa[0] = pk[2*kt2][0];
            pa[1] = pk[2*kt2][1];
            pa[2] = pk[2*kt2 + 1][0];
            pa[3] = pk[2*kt2 + 1][1];
#pragma unroll
            for (int ni = 0; ni < 8; ni++) {
                unsigned bv[2];
                bv[0] = *(const unsigned*)&Vt[ni*8 + g][kt2*16 + 2*l];
                bv[1] = *(const unsigned*)&Vt[ni*8 + g][kt2*16 + 2*l + 8];
                mma_f16(oa[ni], pa, bv);
            }
        }
    }

    // final: reduce l over quad, normalize, store [B,T,D]
    l0 += __shfl_xor_sync(0xffffffffu, l0, 1);
    l0 += __shfl_xor_sync(0xffffffffu, l0, 2);
    l1 += __shfl_xor_sync(0xffffffffu, l1, 1);
    l1 += __shfl_xor_sync(0xffffffffu, l1, 2);
    float i0 = 1.0f / l0;
    float i1 = 1.0f / l1;

    float* ob = O + ((size_t)(b * T_ + mrow0)) * D_ + h * DH;
#pragma unroll
    for (int ni = 0; ni < 8; ni++) {
        float2 v0; v0.x = oa[ni][0] * i0; v0.y = oa[ni][1] * i0;
        float2 v1; v1.x = oa[ni][2] * i1; v1.y = oa[ni][3] * i1;
        *(float2*)(ob + (size_t)g       * D_ + ni*8 + 2*l) = v0;
        *(float2*)(ob + (size_t)(g + 8) * D_ + ni*8 + 2*l) = v1;
    }
}

// ===========================================================================
extern "C" void kernel_launch(void* const* d_in, const int* in_sizes, int n_in,
                              void* d_out, int out_size)
{
    (void)in_sizes; (void)n_in; (void)out_size;
    const float* x    = (const float*)d_in[0];
    const int*   mask = (const int*)  d_in[1];
    const float* Wq   = (const float*)d_in[2];
    const float* bq   = (const float*)d_in[3];
    const float* Wk   = (const float*)d_in[4];
    const float* bk   = (const float*)d_in[5];
    const float* Wv   = (const float*)d_in[6];
    const float* bv   = (const float*)d_in[7];
    const float* Wo   = (const float*)d_in[8];
    const float* bo   = (const float*)d_in[9];
    float* out = (float*)d_out;

    float *q, *k, *v, *attn;
    cudaGetSymbolAddress((void**)&q,    g_q);
    cudaGetSymbolAddress((void**)&k,    g_k);
    cudaGetSymbolAddress((void**)&v,    g_v);
    cudaGetSymbolAddress((void**)&attn, g_attn);

    mma_gemm<<<dim3(D_/128, M_/128, 3), 256>>>(
        x, Wq, bq, q, Wk, bk, k, Wv, bv, v, 1);

    attn_mma_kernel<<<dim3(T_/FBM, B_*H_), 128>>>(q, k, v, mask, attn);

    mma_gemm<<<dim3(D_/128, M_/128, 1), 256>>>(
        attn, Wo, bo, out, Wo, bo, out, Wo, bo, out, 0);
}

// round 5
// speedup vs baseline: 6.1171x; 1.8791x over previous
#include <cuda_runtime.h>
#include <cuda_fp16.h>
#include <cstdint>
#include <math.h>

#define B_  2
#define T_  2048
#define D_  1024
#define H_  16
#define DH  64
#define M_  (B_*T_)
#define NEG_INF_F (-1.0e9f)
#define QSC 0.18033688011112042f   // 0.125 * log2(e)

// Scratch (allocation-free rule: __device__ globals)
__device__ __half g_qh[(size_t)B_*H_*T_*DH];
__device__ __half g_kh[(size_t)B_*H_*T_*DH];
__device__ __half g_vh[(size_t)B_*H_*T_*DH];
__device__ float  g_attn[(size_t)M_*D_];

// ===========================================================================
// helpers
// ===========================================================================
__device__ __forceinline__ unsigned packh2(float lo, float hi) {
    __half2 h = __floats2half2_rn(lo, hi);
    return *(unsigned*)&h;
}
__device__ __forceinline__ float ex2(float x) {
    float y;
    asm("ex2.approx.ftz.f32 %0, %1;" : "=f"(y) : "f"(x));
    return y;
}
__device__ __forceinline__ uint32_t smaddr(const void* p) {
    return (uint32_t)__cvta_generic_to_shared(p);
}
__device__ __forceinline__ void mma_f16(float* c, const unsigned* a, const unsigned* b) {
    asm volatile(
        "mma.sync.aligned.m16n8k16.row.col.f32.f16.f16.f32 "
        "{%0,%1,%2,%3}, {%4,%5,%6,%7}, {%8,%9}, {%0,%1,%2,%3};\n"
        : "+f"(c[0]), "+f"(c[1]), "+f"(c[2]), "+f"(c[3])
        : "r"(a[0]), "r"(a[1]), "r"(a[2]), "r"(a[3]),
          "r"(b[0]), "r"(b[1]));
}
__device__ __forceinline__ void ldsm_x4(unsigned* r, uint32_t a) {
    asm volatile("ldmatrix.sync.aligned.m8n8.x4.shared.b16 {%0,%1,%2,%3}, [%4];"
        : "=r"(r[0]), "=r"(r[1]), "=r"(r[2]), "=r"(r[3]) : "r"(a));
}
__device__ __forceinline__ void ldsm_x2(unsigned* r, uint32_t a) {
    asm volatile("ldmatrix.sync.aligned.m8n8.x2.shared.b16 {%0,%1}, [%2];"
        : "=r"(r[0]), "=r"(r[1]) : "r"(a));
}
__device__ __forceinline__ void ldsm_x2t(unsigned* r, uint32_t a) {
    asm volatile("ldmatrix.sync.aligned.m8n8.x2.trans.shared.b16 {%0,%1}, [%2];"
        : "=r"(r[0]), "=r"(r[1]) : "r"(a));
}
__device__ __forceinline__ void cpasync16(uint32_t dst, const void* src) {
    asm volatile("cp.async.cg.shared.global [%0], [%1], 16;" :: "r"(dst), "l"(src));
}

// ===========================================================================
// fp16 tensor-core GEMM: C = A[M,1024] @ W[1024,1024]^T + bias
// 128x128 tile, BK=32, double-buffered smem, ldmatrix fragment loads.
// mode 0: fp32 C[m*1024+n].  mode 1: fp16 qkv layout [B,H,T,dh], z=0 scaled.
// ===========================================================================
#define GP 20            // smem word pitch (16 data words + 4 pad)
#define GBUFB (128*GP*4) // bytes per buffer

__global__ __launch_bounds__(256) void mma_gemm_f16(
    const float* __restrict__ A,
    const float* __restrict__ W0, const float* __restrict__ bb0, void* __restrict__ C0,
    const float* __restrict__ W1, const float* __restrict__ bb1, void* __restrict__ C1,
    const float* __restrict__ W2, const float* __restrict__ bb2, void* __restrict__ C2,
    int mode, float scale0)
{
    const int z = blockIdx.z;
    const float* W    = (z == 0) ? W0  : (z == 1) ? W1  : W2;
    const float* bias = (z == 0) ? bb0 : (z == 1) ? bb1 : bb2;
    void* C           = (z == 0) ? C0  : (z == 1) ? C1  : C2;
    const float sc    = (z == 0) ? scale0 : 1.0f;

    __shared__ unsigned As[2][128][GP];
    __shared__ unsigned Ws[2][128][GP];

    const int tid  = threadIdx.x;
    const int warp = tid >> 5, lane = tid & 31;
    const int g = lane >> 2, l = lane & 3;
    const int wm = (warp >> 2) * 64;
    const int wn = (warp & 3) * 32;
    const int m0 = blockIdx.y * 128;
    const int n0 = blockIdx.x * 128;

    const int lrow = tid >> 3;
    const int lcf  = (tid & 7) * 4;   // float col within K-tile
    const int lcw  = (tid & 7) * 2;   // word col in smem

    // ldmatrix byte offsets within a buffer
    const int a_base = ((wm + (lane & 15)) * GP + (lane >> 4) * 4) * 4;
    const int b_base = ((wn + (lane & 7)) * GP + ((lane >> 3) & 1) * 4) * 4;
    const uint32_t sA0 = smaddr(&As[0][0][0]);
    const uint32_t sW0 = smaddr(&Ws[0][0][0]);

    float acc[4][4][4];
#pragma unroll
    for (int mi = 0; mi < 4; mi++)
#pragma unroll
        for (int ni = 0; ni < 4; ni++)
#pragma unroll
            for (int e = 0; e < 4; e++) acc[mi][ni][e] = 0.0f;

    float4 stA[4], stW[4];
#pragma unroll
    for (int j = 0; j < 4; j++) {
        int row = lrow + j * 32;
        stA[j] = *(const float4*)(A + (size_t)(m0 + row) * D_ + lcf);
        stW[j] = *(const float4*)(W + (size_t)(n0 + row) * D_ + lcf);
    }
#pragma unroll
    for (int j = 0; j < 4; j++) {
        int row = lrow + j * 32;
        uint2 ua; ua.x = packh2(stA[j].x, stA[j].y); ua.y = packh2(stA[j].z, stA[j].w);
        *(uint2*)&As[0][row][lcw] = ua;
        uint2 uw; uw.x = packh2(stW[j].x, stW[j].y); uw.y = packh2(stW[j].z, stW[j].w);
        *(uint2*)&Ws[0][row][lcw] = uw;
    }
    __syncthreads();

    for (int kt = 0; kt < 32; kt++) {
        const int buf = kt & 1;
        const bool has_next = (kt < 31);
        if (has_next) {
            const int kg = (kt + 1) * 32 + lcf;
#pragma unroll
            for (int j = 0; j < 4; j++) {
                int row = lrow + j * 32;
                stA[j] = *(const float4*)(A + (size_t)(m0 + row) * D_ + kg);
                stW[j] = *(const float4*)(W + (size_t)(n0 + row) * D_ + kg);
            }
        }

        const uint32_t aB = sA0 + buf * GBUFB;
        const uint32_t bB = sW0 + buf * GBUFB;
#pragma unroll
        for (int kk = 0; kk < 2; kk++) {
            unsigned af[4][4], bf[4][2];
#pragma unroll
            for (int mi = 0; mi < 4; mi++)
                ldsm_x4(af[mi], aB + a_base + mi * (16 * GP * 4) + kk * 32);
#pragma unroll
            for (int ni = 0; ni < 4; ni++)
                ldsm_x2(bf[ni], bB + b_base + ni * (8 * GP * 4) + kk * 32);
#pragma unroll
            for (int mi = 0; mi < 4; mi++)
#pragma unroll
                for (int ni = 0; ni < 4; ni++)
                    mma_f16(acc[mi][ni], af[mi], bf[ni]);
        }

        if (has_next) {
            const int nb = buf ^ 1;
#pragma unroll
            for (int j = 0; j < 4; j++) {
                int row = lrow + j * 32;
                uint2 ua; ua.x = packh2(stA[j].x, stA[j].y); ua.y = packh2(stA[j].z, stA[j].w);
                *(uint2*)&As[nb][row][lcw] = ua;
                uint2 uw; uw.x = packh2(stW[j].x, stW[j].y); uw.y = packh2(stW[j].z, stW[j].w);
                *(uint2*)&Ws[nb][row][lcw] = uw;
            }
        }
        __syncthreads();
    }

    // epilogue
#pragma unroll
    for (int ni = 0; ni < 4; ni++) {
        int n = n0 + wn + ni * 8 + 2 * l;
        float bv0 = __ldg(bias + n);
        float bv1 = __ldg(bias + n + 1);
#pragma unroll
        for (int mi = 0; mi < 4; mi++) {
            int m = m0 + wm + mi * 16 + g;
#pragma unroll
            for (int half_ = 0; half_ < 2; half_++) {
                int mm = m + half_ * 8;
                float v0 = acc[mi][ni][half_ * 2 + 0] + bv0;
                float v1 = acc[mi][ni][half_ * 2 + 1] + bv1;
                if (mode == 0) {
                    float2 v; v.x = v0; v.y = v1;
                    *(float2*)((float*)C + (size_t)mm * D_ + n) = v;
                } else {
                    int bb = mm >> 11;
                    int t  = mm & (T_ - 1);
                    int hh = n >> 6;
                    int d  = n & (DH - 1);
                    unsigned hv = packh2(v0 * sc, v1 * sc);
                    *(unsigned*)((__half*)C + (((size_t)(bb * H_ + hh)) * T_ + t) * DH + d) = hv;
                }
            }
        }
    }
}

// ===========================================================================
// fp16 flash attention: BM=128 (8 warps), BN=64, dh=64.
// cp.async double-buffered K/V tiles (fp16, row-major), ldmatrix frags,
// V via ldmatrix.trans (no transpose pass). exp2-domain softmax (scale folded
// into q at QKV epilogue). Output fp32 [B,T,D].
// ===========================================================================
#define FBM 128
#define FBN 64
#define KPW 36            // smem word pitch (72 halves)
#define ATB (FBN*72*2)    // bytes per K (or V) buffer = 9216

__global__ __launch_bounds__(256) void attn_f16(
    const __half* __restrict__ Qh, const __half* __restrict__ Kh,
    const __half* __restrict__ Vh, const int* __restrict__ mask,
    float* __restrict__ O)
{
    __shared__ __half Ks[2][FBN][72];
    __shared__ __half Vs[2][FBN][72];
    __shared__ int    Mall[T_];

    const int bh = blockIdx.y;
    const int b  = bh >> 4;
    const int h  = bh & (H_ - 1);
    const int tid  = threadIdx.x;
    const int warp = tid >> 5, lane = tid & 31;
    const int g = lane >> 2, l = lane & 3;
    const int mrow0 = blockIdx.x * FBM + warp * 16;

    for (int i = tid; i < T_; i += 256) Mall[i] = mask[b * T_ + i];

    // Q fragments (already scaled by 0.125*log2e at QKV epilogue)
    unsigned qf[4][4];
    {
        const __half* qb = Qh + ((size_t)bh * T_ + mrow0) * DH;
#pragma unroll
        for (int kt = 0; kt < 4; kt++) {
            qf[kt][0] = *(const unsigned*)(qb + (size_t)g       * DH + kt*16 + 2*l);
            qf[kt][1] = *(const unsigned*)(qb + (size_t)(g + 8) * DH + kt*16 + 2*l);
            qf[kt][2] = *(const unsigned*)(qb + (size_t)g       * DH + kt*16 + 2*l + 8);
            qf[kt][3] = *(const unsigned*)(qb + (size_t)(g + 8) * DH + kt*16 + 2*l + 8);
        }
    }

    float oa[8][4];
#pragma unroll
    for (int ni = 0; ni < 8; ni++)
#pragma unroll
        for (int e = 0; e < 4; e++) oa[ni][e] = 0.0f;
    float m0 = -INFINITY, m1 = -INFINITY;
    float l0 = 0.0f, l1 = 0.0f;

    const __half* kb0 = Kh + (size_t)bh * T_ * DH;
    const __half* vb0 = Vh + (size_t)bh * T_ * DH;
    const uint32_t ks0 = smaddr(&Ks[0][0][0]);
    const uint32_t vs0 = smaddr(&Vs[0][0][0]);

    // per-thread tile-load mapping: 2 x 16B chunks per tensor
    const int crow0 = tid >> 3;          // rows crow0, crow0+32
    const int cc8   = (tid & 7) * 8;     // half col
    const int cdst  = (crow0 * 72 + cc8) * 2;

    // prologue: tile 0 -> buf 0
    {
        const __half* ksrc = kb0 + (size_t)crow0 * DH + cc8;
        const __half* vsrc = vb0 + (size_t)crow0 * DH + cc8;
        cpasync16(ks0 + cdst, ksrc);
        cpasync16(vs0 + cdst, vsrc);
        cpasync16(ks0 + cdst + 32 * 144, ksrc + 32 * DH);
        cpasync16(vs0 + cdst + 32 * 144, vsrc + 32 * DH);
        asm volatile("cp.async.commit_group;");
    }

    const int sbq_base = ((lane & 7) * KPW + ((lane >> 3) & 1) * 4) * 4;
    const int pvb_base = ((lane & 15) * KPW) * 4;

    for (int t = 0; t < 32; t++) {
        const int buf = t & 1;
        const bool has_next = (t < 31);
        if (has_next) {
            const int nb = buf ^ 1;
            const __half* ksrc = kb0 + (size_t)((t + 1) * FBN + crow0) * DH + cc8;
            const __half* vsrc = vb0 + (size_t)((t + 1) * FBN + crow0) * DH + cc8;
            cpasync16(ks0 + nb * ATB + cdst, ksrc);
            cpasync16(vs0 + nb * ATB + cdst, vsrc);
            cpasync16(ks0 + nb * ATB + cdst + 32 * 144, ksrc + 32 * DH);
            cpasync16(vs0 + nb * ATB + cdst + 32 * 144, vsrc + 32 * DH);
            asm volatile("cp.async.commit_group;");
            asm volatile("cp.async.wait_group 1;");
        } else {
            asm volatile("cp.async.wait_group 0;");
        }
        __syncthreads();

        // S = Q K^T
        float sa[8][4];
#pragma unroll
        for (int ni = 0; ni < 8; ni++)
#pragma unroll
            for (int e = 0; e < 4; e++) sa[ni][e] = 0.0f;
        const uint32_t kbase = ks0 + buf * ATB;
#pragma unroll
        for (int kt = 0; kt < 4; kt++) {
#pragma unroll
            for (int ni = 0; ni < 8; ni++) {
                unsigned bq[2];
                ldsm_x2(bq, kbase + sbq_base + ni * 1152 + kt * 32);
                mma_f16(sa[ni], qf[kt], bq);
            }
        }

        // mask (scores already in log2 domain)
        const int mb = t * FBN;
#pragma unroll
        for (int ni = 0; ni < 8; ni++) {
            int c0m = Mall[mb + ni*8 + 2*l];
            int c1m = Mall[mb + ni*8 + 2*l + 1];
            if (!c0m) { sa[ni][0] = NEG_INF_F; sa[ni][2] = NEG_INF_F; }
            if (!c1m) { sa[ni][1] = NEG_INF_F; sa[ni][3] = NEG_INF_F; }
        }

        float rm0 = -INFINITY, rm1 = -INFINITY;
#pragma unroll
        for (int ni = 0; ni < 8; ni++) {
            rm0 = fmaxf(rm0, fmaxf(sa[ni][0], sa[ni][1]));
            rm1 = fmaxf(rm1, fmaxf(sa[ni][2], sa[ni][3]));
        }
        rm0 = fmaxf(rm0, __shfl_xor_sync(0xffffffffu, rm0, 1));
        rm0 = fmaxf(rm0, __shfl_xor_sync(0xffffffffu, rm0, 2));
        rm1 = fmaxf(rm1, __shfl_xor_sync(0xffffffffu, rm1, 1));
        rm1 = fmaxf(rm1, __shfl_xor_sync(0xffffffffu, rm1, 2));
        float mn0 = fmaxf(m0, rm0);
        float mn1 = fmaxf(m1, rm1);
        float cr0 = ex2(m0 - mn0);
        float cr1 = ex2(m1 - mn1);

        unsigned pk[8][2];
        float ts0 = 0.0f, ts1 = 0.0f;
#pragma unroll
        for (int ni = 0; ni < 8; ni++) {
            float e0 = ex2(sa[ni][0] - mn0);
            float e1 = ex2(sa[ni][1] - mn0);
            float e2 = ex2(sa[ni][2] - mn1);
            float e3 = ex2(sa[ni][3] - mn1);
            ts0 += e0 + e1;
            ts1 += e2 + e3;
            pk[ni][0] = packh2(e0, e1);
            pk[ni][1] = packh2(e2, e3);
        }
        l0 = l0 * cr0 + ts0;
        l1 = l1 * cr1 + ts1;
#pragma unroll
        for (int ni = 0; ni < 8; ni++) {
            oa[ni][0] *= cr0; oa[ni][1] *= cr0;
            oa[ni][2] *= cr1; oa[ni][3] *= cr1;
        }
        m0 = mn0; m1 = mn1;

        // O += P V  (V b-frags via ldmatrix.trans on row-major tile)
        const uint32_t vbase = vs0 + buf * ATB;
#pragma unroll
        for (int kt2 = 0; kt2 < 4; kt2++) {
            unsigned pa[4];
            pa[0] = pk[2*kt2][0];
            pa[1] = pk[2*kt2][1];
            pa[2] = pk[2*kt2 + 1][0];
            pa[3] = pk[2*kt2 + 1][1];
#pragma unroll
            for (int ni = 0; ni < 8; ni++) {
                unsigned bv[2];
                ldsm_x2t(bv, vbase + pvb_base + kt2 * 2304 + ni * 16);
                mma_f16(oa[ni], pa, bv);
            }
        }
        __syncthreads();
    }

    l0 += __shfl_xor_sync(0xffffffffu, l0, 1);
    l0 += __shfl_xor_sync(0xffffffffu, l0, 2);
    l1 += __shfl_xor_sync(0xffffffffu, l1, 1);
    l1 += __shfl_xor_sync(0xffffffffu, l1, 2);
    float i0 = 1.0f / l0;
    float i1 = 1.0f / l1;

    float* ob = O + ((size_t)(b * T_ + mrow0)) * D_ + h * DH;
#pragma unroll
    for (int ni = 0; ni < 8; ni++) {
        float2 v0; v0.x = oa[ni][0] * i0; v0.y = oa[ni][1] * i0;
        float2 v1; v1.x = oa[ni][2] * i1; v1.y = oa[ni][3] * i1;
        *(float2*)(ob + (size_t)g       * D_ + ni*8 + 2*l) = v0;
        *(float2*)(ob + (size_t)(g + 8) * D_ + ni*8 + 2*l) = v1;
    }
}

// ===========================================================================
extern "C" void kernel_launch(void* const* d_in, const int* in_sizes, int n_in,
                              void* d_out, int out_size)
{
    (void)in_sizes; (void)n_in; (void)out_size;
    const float* x    = (const float*)d_in[0];
    const int*   mask = (const int*)  d_in[1];
    const float* Wq   = (const float*)d_in[2];
    const float* bq   = (const float*)d_in[3];
    const float* Wk   = (const float*)d_in[4];
    const float* bk   = (const float*)d_in[5];
    const float* Wv   = (const float*)d_in[6];
    const float* bv   = (const float*)d_in[7];
    const float* Wo   = (const float*)d_in[8];
    const float* bo   = (const float*)d_in[9];
    float* out = (float*)d_out;

    __half *q, *k, *v; float* attn;
    cudaGetSymbolAddress((void**)&q,    g_qh);
    cudaGetSymbolAddress((void**)&k,    g_kh);
    cudaGetSymbolAddress((void**)&v,    g_vh);
    cudaGetSymbolAddress((void**)&attn, g_attn);

    // fused QKV projections (fp16 out, q pre-scaled by 0.125*log2e)
    mma_gemm_f16<<<dim3(D_/128, M_/128, 3), 256>>>(
        x, Wq, bq, q, Wk, bk, k, Wv, bv, v, 1, QSC);

    attn_f16<<<dim3(T_/FBM, B_*H_), 256>>>(q, k, v, mask, attn);

    // output projection (fp32 out)
    mma_gemm_f16<<<dim3(D_/128, M_/128, 1), 256>>>(
        attn, Wo, bo, out, Wo, bo, out, Wo, bo, out, 0, 1.0f);
}

// round 6
// speedup vs baseline: 7.3776x; 1.2061x over previous
#include <cuda_runtime.h>
#include <cuda_fp16.h>
#include <cstdint>
#include <math.h>

#define B_  2
#define T_  2048
#define D_  1024
#define H_  16
#define DH  64
#define M_  (B_*T_)
#define NEG_INF_F (-1.0e9f)
#define QSC 0.18033688011112042f   // 0.125 * log2(e)

// Scratch (allocation-free rule: __device__ globals)
__device__ __half g_qh[(size_t)B_*H_*T_*DH];
__device__ __half g_kh[(size_t)B_*H_*T_*DH];
__device__ __half g_vh[(size_t)B_*H_*T_*DH];
__device__ __half g_attn[(size_t)M_*D_];
__device__ __half g_xh[(size_t)M_*D_];
__device__ __half g_wh[(size_t)4*D_*D_];

// ===========================================================================
// helpers
// ===========================================================================
__device__ __forceinline__ unsigned packh2(float lo, float hi) {
    __half2 h = __floats2half2_rn(lo, hi);
    return *(unsigned*)&h;
}
__device__ __forceinline__ float ex2(float x) {
    float y;
    asm("ex2.approx.ftz.f32 %0, %1;" : "=f"(y) : "f"(x));
    return y;
}
__device__ __forceinline__ uint32_t smaddr(const void* p) {
    return (uint32_t)__cvta_generic_to_shared(p);
}
__device__ __forceinline__ void mma_f16(float* c, const unsigned* a, const unsigned* b) {
    asm volatile(
        "mma.sync.aligned.m16n8k16.row.col.f32.f16.f16.f32 "
        "{%0,%1,%2,%3}, {%4,%5,%6,%7}, {%8,%9}, {%0,%1,%2,%3};\n"
        : "+f"(c[0]), "+f"(c[1]), "+f"(c[2]), "+f"(c[3])
        : "r"(a[0]), "r"(a[1]), "r"(a[2]), "r"(a[3]),
          "r"(b[0]), "r"(b[1]));
}
__device__ __forceinline__ void ldsm_x4(unsigned* r, uint32_t a) {
    asm volatile("ldmatrix.sync.aligned.m8n8.x4.shared.b16 {%0,%1,%2,%3}, [%4];"
        : "=r"(r[0]), "=r"(r[1]), "=r"(r[2]), "=r"(r[3]) : "r"(a));
}
__device__ __forceinline__ void ldsm_x2(unsigned* r, uint32_t a) {
    asm volatile("ldmatrix.sync.aligned.m8n8.x2.shared.b16 {%0,%1}, [%2];"
        : "=r"(r[0]), "=r"(r[1]) : "r"(a));
}
__device__ __forceinline__ void ldsm_x2t(unsigned* r, uint32_t a) {
    asm volatile("ldmatrix.sync.aligned.m8n8.x2.trans.shared.b16 {%0,%1}, [%2];"
        : "=r"(r[0]), "=r"(r[1]) : "r"(a));
}
__device__ __forceinline__ void cpasync16(uint32_t dst, const void* src) {
    asm volatile("cp.async.cg.shared.global [%0], [%1], 16;" :: "r"(dst), "l"(src));
}

// ===========================================================================
// fp32 -> fp16 conversion for x (1M float4) and 4 weight matrices (256K each)
// ===========================================================================
__global__ __launch_bounds__(256) void convert_all(
    const float* __restrict__ x,
    const float* __restrict__ wq, const float* __restrict__ wk,
    const float* __restrict__ wv, const float* __restrict__ wo,
    __half* __restrict__ xh, __half* __restrict__ wh)
{
    const int idx = blockIdx.x * 256 + threadIdx.x;   // 0 .. 2M-1 (float4 units)
    const float* src;
    __half* dst;
    if (idx < (1 << 20)) {
        src = x + (size_t)idx * 4;
        dst = xh + (size_t)idx * 4;
    } else {
        int j = idx - (1 << 20);
        int w = j >> 18;
        int off = j & ((1 << 18) - 1);
        const float* ws = (w == 0) ? wq : (w == 1) ? wk : (w == 2) ? wv : wo;
        src = ws + (size_t)off * 4;
        dst = wh + ((size_t)w << 20) + (size_t)off * 4;
    }
    float4 v = *(const float4*)src;
    uint2 u;
    u.x = packh2(v.x, v.y);
    u.y = packh2(v.z, v.w);
    *(uint2*)dst = u;
}

// ===========================================================================
// fp16 tensor-core GEMM: C = A[M,1024] @ W[1024,1024]^T + bias
// fp16 operands loaded via cp.async (double-buffered, eager commit).
// 128x128 tile, BK=32, 256 threads, 2 CTAs/SM.
// mode 0: fp32 C[m*1024+n].  mode 1: fp16 qkv layout [B,H,T,dh], z=0 scaled.
// W = Wbase + z*2^20.
// ===========================================================================
#define GP 20            // smem word pitch (16 data words + 4 pad) = 80 bytes
#define GBUFB (128*GP*4) // bytes per buffer

__global__ __launch_bounds__(256, 2) void mma_gemm_f16(
    const __half* __restrict__ A, const __half* __restrict__ Wbase,
    const float* __restrict__ bb0, void* __restrict__ C0,
    const float* __restrict__ bb1, void* __restrict__ C1,
    const float* __restrict__ bb2, void* __restrict__ C2,
    int mode, float scale0)
{
    const int z = blockIdx.z;
    const __half* W   = Wbase + ((size_t)z << 20);
    const float* bias = (z == 0) ? bb0 : (z == 1) ? bb1 : bb2;
    void* C           = (z == 0) ? C0  : (z == 1) ? C1  : C2;
    const float sc    = (z == 0) ? scale0 : 1.0f;

    __shared__ unsigned As[2][128][GP];
    __shared__ unsigned Ws[2][128][GP];

    const int tid  = threadIdx.x;
    const int warp = tid >> 5, lane = tid & 31;
    const int g = lane >> 2, l = lane & 3;
    const int wm = (warp >> 2) * 64;
    const int wn = (warp & 3) * 32;
    const int m0 = blockIdx.y * 128;
    const int n0 = blockIdx.x * 128;

    // cp.async mapping: rows crow, crow+64; 16B chunk col (tid&3)
    const int crow = tid >> 2;            // 0..63
    const int cch  = (tid & 3) * 8;       // half offset within 32-half row
    const int cdst = crow * 80 + (tid & 3) * 16;   // byte offset in buffer

    // ldmatrix byte offsets within a buffer
    const int a_base = ((wm + (lane & 15)) * GP + (lane >> 4) * 4) * 4;
    const int b_base = ((wn + (lane & 7)) * GP + ((lane >> 3) & 1) * 4) * 4;
    const uint32_t sA0 = smaddr(&As[0][0][0]);
    const uint32_t sW0 = smaddr(&Ws[0][0][0]);

    float acc[4][4][4];
#pragma unroll
    for (int mi = 0; mi < 4; mi++)
#pragma unroll
        for (int ni = 0; ni < 4; ni++)
#pragma unroll
            for (int e = 0; e < 4; e++) acc[mi][ni][e] = 0.0f;

    // prologue: stage 0 -> buf 0
    {
        const __half* as = A + (size_t)(m0 + crow) * D_ + cch;
        const __half* ws = W + (size_t)(n0 + crow) * D_ + cch;
        cpasync16(sA0 + cdst, as);
        cpasync16(sW0 + cdst, ws);
        cpasync16(sA0 + cdst + 64 * 80, as + 64 * D_);
        cpasync16(sW0 + cdst + 64 * 80, ws + 64 * D_);
        asm volatile("cp.async.commit_group;");
    }

    for (int kt = 0; kt < 32; kt++) {
        const int buf = kt & 1;
        const bool has_next = (kt < 31);
        if (has_next) {
            const int nb = buf ^ 1;
            const int kg = (kt + 1) * 32 + cch;
            const __half* as = A + (size_t)(m0 + crow) * D_ + kg;
            const __half* ws = W + (size_t)(n0 + crow) * D_ + kg;
            cpasync16(sA0 + nb * GBUFB + cdst, as);
            cpasync16(sW0 + nb * GBUFB + cdst, ws);
            cpasync16(sA0 + nb * GBUFB + cdst + 64 * 80, as + 64 * D_);
            cpasync16(sW0 + nb * GBUFB + cdst + 64 * 80, ws + 64 * D_);
            asm volatile("cp.async.commit_group;");
            asm volatile("cp.async.wait_group 1;");
        } else {
            asm volatile("cp.async.wait_group 0;");
        }
        __syncthreads();

        const uint32_t aB = sA0 + buf * GBUFB;
        const uint32_t bB = sW0 + buf * GBUFB;
#pragma unroll
        for (int kk = 0; kk < 2; kk++) {
            unsigned af[4][4], bf[4][2];
#pragma unroll
            for (int mi = 0; mi < 4; mi++)
                ldsm_x4(af[mi], aB + a_base + mi * (16 * GP * 4) + kk * 32);
#pragma unroll
            for (int ni = 0; ni < 4; ni++)
                ldsm_x2(bf[ni], bB + b_base + ni * (8 * GP * 4) + kk * 32);
#pragma unroll
            for (int mi = 0; mi < 4; mi++)
#pragma unroll
                for (int ni = 0; ni < 4; ni++)
                    mma_f16(acc[mi][ni], af[mi], bf[ni]);
        }
        __syncthreads();
    }

    // epilogue
#pragma unroll
    for (int ni = 0; ni < 4; ni++) {
        int n = n0 + wn + ni * 8 + 2 * l;
        float bv0 = __ldg(bias + n);
        float bv1 = __ldg(bias + n + 1);
#pragma unroll
        for (int mi = 0; mi < 4; mi++) {
            int m = m0 + wm + mi * 16 + g;
#pragma unroll
            for (int half_ = 0; half_ < 2; half_++) {
                int mm = m + half_ * 8;
                float v0 = acc[mi][ni][half_ * 2 + 0] + bv0;
                float v1 = acc[mi][ni][half_ * 2 + 1] + bv1;
                if (mode == 0) {
                    float2 v; v.x = v0; v.y = v1;
                    *(float2*)((float*)C + (size_t)mm * D_ + n) = v;
                } else {
                    int bb = mm >> 11;
                    int t  = mm & (T_ - 1);
                    int hh = n >> 6;
                    int d  = n & (DH - 1);
                    unsigned hv = packh2(v0 * sc, v1 * sc);
                    *(unsigned*)((__half*)C + (((size_t)(bb * H_ + hh)) * T_ + t) * DH + d) = hv;
                }
            }
        }
    }
}

// ===========================================================================
// fp16 flash attention: BM=128 (8 warps), BN=64, dh=64.
// cp.async double-buffered K/V tiles, ldmatrix frags, V via ldmatrix.trans.
// exp2-domain softmax (scale pre-folded into q). Output fp16 [B,T,D].
// ===========================================================================
#define FBM 128
#define FBN 64
#define KPW 36            // smem word pitch (72 halves)
#define ATB (FBN*72*2)    // bytes per K (or V) buffer = 9216

__global__ __launch_bounds__(256) void attn_f16(
    const __half* __restrict__ Qh, const __half* __restrict__ Kh,
    const __half* __restrict__ Vh, const int* __restrict__ mask,
    __half* __restrict__ O)
{
    __shared__ __half Ks[2][FBN][72];
    __shared__ __half Vs[2][FBN][72];
    __shared__ int    Mall[T_];

    const int bh = blockIdx.y;
    const int b  = bh >> 4;
    const int h  = bh & (H_ - 1);
    const int tid  = threadIdx.x;
    const int warp = tid >> 5, lane = tid & 31;
    const int g = lane >> 2, l = lane & 3;
    const int mrow0 = blockIdx.x * FBM + warp * 16;

    for (int i = tid; i < T_; i += 256) Mall[i] = mask[b * T_ + i];

    // Q fragments (already scaled by 0.125*log2e at QKV epilogue)
    unsigned qf[4][4];
    {
        const __half* qb = Qh + ((size_t)bh * T_ + mrow0) * DH;
#pragma unroll
        for (int kt = 0; kt < 4; kt++) {
            qf[kt][0] = *(const unsigned*)(qb + (size_t)g       * DH + kt*16 + 2*l);
            qf[kt][1] = *(const unsigned*)(qb + (size_t)(g + 8) * DH + kt*16 + 2*l);
            qf[kt][2] = *(const unsigned*)(qb + (size_t)g       * DH + kt*16 + 2*l + 8);
            qf[kt][3] = *(const unsigned*)(qb + (size_t)(g + 8) * DH + kt*16 + 2*l + 8);
        }
    }

    float oa[8][4];
#pragma unroll
    for (int ni = 0; ni < 8; ni++)
#pragma unroll
        for (int e = 0; e < 4; e++) oa[ni][e] = 0.0f;
    float m0 = -INFINITY, m1 = -INFINITY;
    float l0 = 0.0f, l1 = 0.0f;

    const __half* kb0 = Kh + (size_t)bh * T_ * DH;
    const __half* vb0 = Vh + (size_t)bh * T_ * DH;
    const uint32_t ks0 = smaddr(&Ks[0][0][0]);
    const uint32_t vs0 = smaddr(&Vs[0][0][0]);

    // per-thread tile-load mapping: 2 x 16B chunks per tensor
    const int crow0 = tid >> 3;          // rows crow0, crow0+32
    const int cc8   = (tid & 7) * 8;     // half col
    const int cdst  = (crow0 * 72 + cc8) * 2;

    // prologue: tile 0 -> buf 0
    {
        const __half* ksrc = kb0 + (size_t)crow0 * DH + cc8;
        const __half* vsrc = vb0 + (size_t)crow0 * DH + cc8;
        cpasync16(ks0 + cdst, ksrc);
        cpasync16(vs0 + cdst, vsrc);
        cpasync16(ks0 + cdst + 32 * 144, ksrc + 32 * DH);
        cpasync16(vs0 + cdst + 32 * 144, vsrc + 32 * DH);
        asm volatile("cp.async.commit_group;");
    }

    const int sbq_base = ((lane & 7) * KPW + ((lane >> 3) & 1) * 4) * 4;
    const int pvb_base = ((lane & 15) * KPW) * 4;

    for (int t = 0; t < 32; t++) {
        const int buf = t & 1;
        const bool has_next = (t < 31);
        if (has_next) {
            const int nb = buf ^ 1;
            const __half* ksrc = kb0 + (size_t)((t + 1) * FBN + crow0) * DH + cc8;
            const __half* vsrc = vb0 + (size_t)((t + 1) * FBN + crow0) * DH + cc8;
            cpasync16(ks0 + nb * ATB + cdst, ksrc);
            cpasync16(vs0 + nb * ATB + cdst, vsrc);
            cpasync16(ks0 + nb * ATB + cdst + 32 * 144, ksrc + 32 * DH);
            cpasync16(vs0 + nb * ATB + cdst + 32 * 144, vsrc + 32 * DH);
            asm volatile("cp.async.commit_group;");
            asm volatile("cp.async.wait_group 1;");
        } else {
            asm volatile("cp.async.wait_group 0;");
        }
        __syncthreads();

        // S = Q K^T
        float sa[8][4];
#pragma unroll
        for (int ni = 0; ni < 8; ni++)
#pragma unroll
            for (int e = 0; e < 4; e++) sa[ni][e] = 0.0f;
        const uint32_t kbase = ks0 + buf * ATB;
#pragma unroll
        for (int kt = 0; kt < 4; kt++) {
#pragma unroll
            for (int ni = 0; ni < 8; ni++) {
                unsigned bq[2];
                ldsm_x2(bq, kbase + sbq_base + ni * 1152 + kt * 32);
                mma_f16(sa[ni], qf[kt], bq);
            }
        }

        // mask (scores already in log2 domain)
        const int mb = t * FBN;
#pragma unroll
        for (int ni = 0; ni < 8; ni++) {
            int c0m = Mall[mb + ni*8 + 2*l];
            int c1m = Mall[mb + ni*8 + 2*l + 1];
            if (!c0m) { sa[ni][0] = NEG_INF_F; sa[ni][2] = NEG_INF_F; }
            if (!c1m) { sa[ni][1] = NEG_INF_F; sa[ni][3] = NEG_INF_F; }
        }

        float rm0 = -INFINITY, rm1 = -INFINITY;
#pragma unroll
        for (int ni = 0; ni < 8; ni++) {
            rm0 = fmaxf(rm0, fmaxf(sa[ni][0], sa[ni][1]));
            rm1 = fmaxf(rm1, fmaxf(sa[ni][2], sa[ni][3]));
        }
        rm0 = fmaxf(rm0, __shfl_xor_sync(0xffffffffu, rm0, 1));
        rm0 = fmaxf(rm0, __shfl_xor_sync(0xffffffffu, rm0, 2));
        rm1 = fmaxf(rm1, __shfl_xor_sync(0xffffffffu, rm1, 1));
        rm1 = fmaxf(rm1, __shfl_xor_sync(0xffffffffu, rm1, 2));
        float mn0 = fmaxf(m0, rm0);
        float mn1 = fmaxf(m1, rm1);
        float cr0 = ex2(m0 - mn0);
        float cr1 = ex2(m1 - mn1);

        unsigned pk[8][2];
        float ts0 = 0.0f, ts1 = 0.0f;
#pragma unroll
        for (int ni = 0; ni < 8; ni++) {
            float e0 = ex2(sa[ni][0] - mn0);
            float e1 = ex2(sa[ni][1] - mn0);
            float e2 = ex2(sa[ni][2] - mn1);
            float e3 = ex2(sa[ni][3] - mn1);
            ts0 += e0 + e1;
            ts1 += e2 + e3;
            pk[ni][0] = packh2(e0, e1);
            pk[ni][1] = packh2(e2, e3);
        }
        l0 = l0 * cr0 + ts0;
        l1 = l1 * cr1 + ts1;
#pragma unroll
        for (int ni = 0; ni < 8; ni++) {
            oa[ni][0] *= cr0; oa[ni][1] *= cr0;
            oa[ni][2] *= cr1; oa[ni][3] *= cr1;
        }
        m0 = mn0; m1 = mn1;

        // O += P V  (V b-frags via ldmatrix.trans on row-major tile)
        const uint32_t vbase = vs0 + buf * ATB;
#pragma unroll
        for (int kt2 = 0; kt2 < 4; kt2++) {
            unsigned pa[4];
            pa[0] = pk[2*kt2][0];
            pa[1] = pk[2*kt2][1];
            pa[2] = pk[2*kt2 + 1][0];
            pa[3] = pk[2*kt2 + 1][1];
#pragma unroll
            for (int ni = 0; ni < 8; ni++) {
                unsigned bv[2];
                ldsm_x2t(bv, vbase + pvb_base + kt2 * 2304 + ni * 16);
                mma_f16(oa[ni], pa, bv);
            }
        }
        __syncthreads();
    }

    l0 += __shfl_xor_sync(0xffffffffu, l0, 1);
    l0 += __shfl_xor_sync(0xffffffffu, l0, 2);
    l1 += __shfl_xor_sync(0xffffffffu, l1, 1);
    l1 += __shfl_xor_sync(0xffffffffu, l1, 2);
    float i0 = 1.0f / l0;
    float i1 = 1.0f / l1;

    __half* ob = O + ((size_t)(b * T_ + mrow0)) * D_ + h * DH;
#pragma unroll
    for (int ni = 0; ni < 8; ni++) {
        unsigned v0 = packh2(oa[ni][0] * i0, oa[ni][1] * i0);
        unsigned v1 = packh2(oa[ni][2] * i1, oa[ni][3] * i1);
        *(unsigned*)(ob + (size_t)g       * D_ + ni*8 + 2*l) = v0;
        *(unsigned*)(ob + (size_t)(g + 8) * D_ + ni*8 + 2*l) = v1;
    }
}

// ===========================================================================
extern "C" void kernel_launch(void* const* d_in, const int* in_sizes, int n_in,
                              void* d_out, int out_size)
{
    (void)in_sizes; (void)n_in; (void)out_size;
    const float* x    = (const float*)d_in[0];
    const int*   mask = (const int*)  d_in[1];
    const float* Wq   = (const float*)d_in[2];
    const float* bq   = (const float*)d_in[3];
    const float* Wk   = (const float*)d_in[4];
    const float* bk   = (const float*)d_in[5];
    const float* Wv   = (const float*)d_in[6];
    const float* bv   = (const float*)d_in[7];
    const float* Wo   = (const float*)d_in[8];
    const float* bo   = (const float*)d_in[9];
    float* out = (float*)d_out;

    __half *q, *k, *v, *attn, *xh, *wh;
    cudaGetSymbolAddress((void**)&q,    g_qh);
    cudaGetSymbolAddress((void**)&k,    g_kh);
    cudaGetSymbolAddress((void**)&v,    g_vh);
    cudaGetSymbolAddress((void**)&attn, g_attn);
    cudaGetSymbolAddress((void**)&xh,   g_xh);
    cudaGetSymbolAddress((void**)&wh,   g_wh);

    // convert x + all weights to fp16 (2M float4 units)
    convert_all<<<8192, 256>>>(x, Wq, Wk, Wv, Wo, xh, wh);

    // fused QKV projections (fp16 out, q pre-scaled by 0.125*log2e)
    mma_gemm_f16<<<dim3(D_/128, M_/128, 3), 256>>>(
        xh, wh, bq, q, bk, k, bv, v, 1, QSC);

    attn_f16<<<dim3(T_/FBM, B_*H_), 256>>>(q, k, v, mask, attn);

    // output projection (fp32 out); W = wh + 3*2^20
    mma_gemm_f16<<<dim3(D_/128, M_/128, 1), 256>>>(
        attn, wh + ((size_t)3 << 20), bo, out, bo, out, bo, out, 0, 1.0f);
}

// round 9
// speedup vs baseline: 7.9647x; 1.0796x over previous
#include <cuda_runtime.h>
#include <cuda_fp16.h>
#include <cstdint>
#include <math.h>

#define B_  2
#define T_  2048
#define D_  1024
#define H_  16
#define DH  64
#define M_  (B_*T_)
#define NEG_INF_F (-1.0e9f)
#define QSC 0.18033688011112042f   // 0.125 * log2(e)

// Scratch (allocation-free rule: __device__ globals)
__device__ __half g_qh[(size_t)B_*H_*T_*DH];
__device__ __half g_kh[(size_t)B_*H_*T_*DH];
__device__ __half g_vh[(size_t)B_*H_*T_*DH];
__device__ __half g_attn[(size_t)M_*D_];
__device__ __half g_xh[(size_t)M_*D_];
__device__ __half g_wh[(size_t)4*D_*D_];

// ===========================================================================
// helpers
// ===========================================================================
__device__ __forceinline__ unsigned packh2(float lo, float hi) {
    __half2 h = __floats2half2_rn(lo, hi);
    return *(unsigned*)&h;
}
__device__ __forceinline__ float ex2(float x) {
    float y;
    asm("ex2.approx.ftz.f32 %0, %1;" : "=f"(y) : "f"(x));
    return y;
}
__device__ __forceinline__ uint32_t smaddr(const void* p) {
    return (uint32_t)__cvta_generic_to_shared(p);
}
__device__ __forceinline__ void mma_f16(float* c, const unsigned* a, const unsigned* b) {
    asm volatile(
        "mma.sync.aligned.m16n8k16.row.col.f32.f16.f16.f32 "
        "{%0,%1,%2,%3}, {%4,%5,%6,%7}, {%8,%9}, {%0,%1,%2,%3};\n"
        : "+f"(c[0]), "+f"(c[1]), "+f"(c[2]), "+f"(c[3])
        : "r"(a[0]), "r"(a[1]), "r"(a[2]), "r"(a[3]),
          "r"(b[0]), "r"(b[1]));
}
__device__ __forceinline__ void ldsm_x4(unsigned* r, uint32_t a) {
    asm volatile("ldmatrix.sync.aligned.m8n8.x4.shared.b16 {%0,%1,%2,%3}, [%4];"
        : "=r"(r[0]), "=r"(r[1]), "=r"(r[2]), "=r"(r[3]) : "r"(a));
}
__device__ __forceinline__ void ldsm_x2(unsigned* r, uint32_t a) {
    asm volatile("ldmatrix.sync.aligned.m8n8.x2.shared.b16 {%0,%1}, [%2];"
        : "=r"(r[0]), "=r"(r[1]) : "r"(a));
}
__device__ __forceinline__ void ldsm_x2t(unsigned* r, uint32_t a) {
    asm volatile("ldmatrix.sync.aligned.m8n8.x2.trans.shared.b16 {%0,%1}, [%2];"
        : "=r"(r[0]), "=r"(r[1]) : "r"(a));
}
__device__ __forceinline__ void cpasync16(uint32_t dst, const void* src) {
    asm volatile("cp.async.cg.shared.global [%0], [%1], 16;" :: "r"(dst), "l"(src));
}

// ===========================================================================
// fp32 -> fp16 conversion for x (1M float4) and 4 weight matrices (256K each)
// ===========================================================================
__global__ __launch_bounds__(256) void convert_all(
    const float* __restrict__ x,
    const float* __restrict__ wq, const float* __restrict__ wk,
    const float* __restrict__ wv, const float* __restrict__ wo,
    __half* __restrict__ xh, __half* __restrict__ wh)
{
    const int idx = blockIdx.x * 256 + threadIdx.x;   // 0 .. 2M-1 (float4 units)
    const float* src;
    __half* dst;
    if (idx < (1 << 20)) {
        src = x + (size_t)idx * 4;
        dst = xh + (size_t)idx * 4;
    } else {
        int j = idx - (1 << 20);
        int w = j >> 18;
        int off = j & ((1 << 18) - 1);
        const float* ws = (w == 0) ? wq : (w == 1) ? wk : (w == 2) ? wv : wo;
        src = ws + (size_t)off * 4;
        dst = wh + ((size_t)w << 20) + (size_t)off * 4;
    }
    float4 v = *(const float4*)src;
    uint2 u;
    u.x = packh2(v.x, v.y);
    u.y = packh2(v.z, v.w);
    *(uint2*)dst = u;
}

// ===========================================================================
// fp16 tensor-core GEMM: C = A[M,1024] @ W[1024,1024]^T + bias
// 128x128 tile, BK=32, 2-stage cp.async pipeline (static smem), ONE
// __syncthreads per K-tile (wait 0; sync; issue next; compute).
// 256 threads, 2 CTAs/SM.
// mode 0: fp32 C[m*1024+n].  mode 1: fp16 qkv layout [B,H,T,dh], z=0 scaled.
// W = Wbase + z*2^20.
// ===========================================================================
#define GP 20            // smem word pitch (16 data words + 4 pad) = 80 bytes
#define GBUFB (128*GP*4) // bytes per buffer = 10240

__global__ __launch_bounds__(256, 2) void mma_gemm_f16(
    const __half* __restrict__ A, const __half* __restrict__ Wbase,
    const float* __restrict__ bb0, void* __restrict__ C0,
    const float* __restrict__ bb1, void* __restrict__ C1,
    const float* __restrict__ bb2, void* __restrict__ C2,
    int mode, float scale0)
{
    const int z = blockIdx.z;
    const __half* W   = Wbase + ((size_t)z << 20);
    const float* bias = (z == 0) ? bb0 : (z == 1) ? bb1 : bb2;
    void* C           = (z == 0) ? C0  : (z == 1) ? C1  : C2;
    const float sc    = (z == 0) ? scale0 : 1.0f;

    __shared__ unsigned As[2][128][GP];
    __shared__ unsigned Ws[2][128][GP];

    const int tid  = threadIdx.x;
    const int warp = tid >> 5, lane = tid & 31;
    const int g = lane >> 2, l = lane & 3;
    const int wm = (warp >> 2) * 64;
    const int wn = (warp & 3) * 32;
    const int m0 = blockIdx.y * 128;
    const int n0 = blockIdx.x * 128;

    // cp.async mapping: rows crow, crow+64; 16B chunk col (tid&3)
    const int crow = tid >> 2;            // 0..63
    const int cch  = (tid & 3) * 8;       // half offset within 32-half row
    const int cdst = crow * 80 + (tid & 3) * 16;   // byte offset in buffer

    // ldmatrix byte offsets within a buffer
    const int a_base = ((wm + (lane & 15)) * GP + (lane >> 4) * 4) * 4;
    const int b_base = ((wn + (lane & 7)) * GP + ((lane >> 3) & 1) * 4) * 4;
    const uint32_t sA0 = smaddr(&As[0][0][0]);
    const uint32_t sW0 = smaddr(&Ws[0][0][0]);

    const __half* Abase = A + (size_t)(m0 + crow) * D_ + cch;
    const __half* Wrow  = W + (size_t)(n0 + crow) * D_ + cch;

    float acc[4][4][4];
#pragma unroll
    for (int mi = 0; mi < 4; mi++)
#pragma unroll
        for (int ni = 0; ni < 4; ni++)
#pragma unroll
            for (int e = 0; e < 4; e++) acc[mi][ni][e] = 0.0f;

    // prologue: tile 0 -> buf 0
    {
        cpasync16(sA0 + cdst, Abase);
        cpasync16(sW0 + cdst, Wrow);
        cpasync16(sA0 + cdst + 64 * 80, Abase + 64 * D_);
        cpasync16(sW0 + cdst + 64 * 80, Wrow + 64 * D_);
        asm volatile("cp.async.commit_group;");
    }

    for (int kt = 0; kt < 32; kt++) {
        const int buf = kt & 1;
        asm volatile("cp.async.wait_group 0;");
        __syncthreads();

        // issue next tile into the other buffer (its compute finished last iter)
        if (kt < 31) {
            const int nb = buf ^ 1;
            const __half* as = Abase + (kt + 1) * 32;
            const __half* ws = Wrow  + (kt + 1) * 32;
            cpasync16(sA0 + nb * GBUFB + cdst, as);
            cpasync16(sW0 + nb * GBUFB + cdst, ws);
            cpasync16(sA0 + nb * GBUFB + cdst + 64 * 80, as + 64 * D_);
            cpasync16(sW0 + nb * GBUFB + cdst + 64 * 80, ws + 64 * D_);
            asm volatile("cp.async.commit_group;");
        }

        const uint32_t aB = sA0 + buf * GBUFB;
        const uint32_t bB = sW0 + buf * GBUFB;
#pragma unroll
        for (int kk = 0; kk < 2; kk++) {
            unsigned af[4][4], bf[4][2];
#pragma unroll
            for (int mi = 0; mi < 4; mi++)
                ldsm_x4(af[mi], aB + a_base + mi * (16 * GP * 4) + kk * 32);
#pragma unroll
            for (int ni = 0; ni < 4; ni++)
                ldsm_x2(bf[ni], bB + b_base + ni * (8 * GP * 4) + kk * 32);
#pragma unroll
            for (int mi = 0; mi < 4; mi++)
#pragma unroll
                for (int ni = 0; ni < 4; ni++)
                    mma_f16(acc[mi][ni], af[mi], bf[ni]);
        }
    }

    // epilogue
#pragma unroll
    for (int ni = 0; ni < 4; ni++) {
        int n = n0 + wn + ni * 8 + 2 * l;
        float bv0 = __ldg(bias + n);
        float bv1 = __ldg(bias + n + 1);
#pragma unroll
        for (int mi = 0; mi < 4; mi++) {
            int m = m0 + wm + mi * 16 + g;
#pragma unroll
            for (int half_ = 0; half_ < 2; half_++) {
                int mm = m + half_ * 8;
                float v0 = acc[mi][ni][half_ * 2 + 0] + bv0;
                float v1 = acc[mi][ni][half_ * 2 + 1] + bv1;
                if (mode == 0) {
                    float2 v; v.x = v0; v.y = v1;
                    *(float2*)((float*)C + (size_t)mm * D_ + n) = v;
                } else {
                    int bb = mm >> 11;
                    int t  = mm & (T_ - 1);
                    int hh = n >> 6;
                    int d  = n & (DH - 1);
                    unsigned hv = packh2(v0 * sc, v1 * sc);
                    *(unsigned*)((__half*)C + (((size_t)(bb * H_ + hh)) * T_ + t) * DH + d) = hv;
                }
            }
        }
    }
}

// ===========================================================================
// fp16 flash attention: BM=128 (8 warps), BN=64, dh=64.
// 2-stage cp.async pipeline, ONE __syncthreads per tile. ldmatrix frags,
// V via ldmatrix.trans. exp2-domain softmax. Output fp16 [B,T,D].
// ===========================================================================
#define FBM 128
#define FBN 64
#define KPW 36            // smem word pitch (72 halves)
#define ATB (FBN*72*2)    // bytes per K (or V) buffer = 9216

__global__ __launch_bounds__(256) void attn_f16(
    const __half* __restrict__ Qh, const __half* __restrict__ Kh,
    const __half* __restrict__ Vh, const int* __restrict__ mask,
    __half* __restrict__ O)
{
    __shared__ __half Ks[2][FBN][72];
    __shared__ __half Vs[2][FBN][72];
    __shared__ int    Mall[T_];

    const int bh = blockIdx.y;
    const int b  = bh >> 4;
    const int h  = bh & (H_ - 1);
    const int tid  = threadIdx.x;
    const int warp = tid >> 5, lane = tid & 31;
    const int g = lane >> 2, l = lane & 3;
    const int mrow0 = blockIdx.x * FBM + warp * 16;

    const __half* kb0 = Kh + (size_t)bh * T_ * DH;
    const __half* vb0 = Vh + (size_t)bh * T_ * DH;
    const uint32_t ks0 = smaddr(&Ks[0][0][0]);
    const uint32_t vs0 = smaddr(&Vs[0][0][0]);

    // per-thread tile-load mapping: 2 x 16B chunks per tensor
    const int crow0 = tid >> 3;          // rows crow0, crow0+32
    const int cc8   = (tid & 7) * 8;     // half col
    const int cdst  = (crow0 * 72 + cc8) * 2;

    // prologue: tile 0 -> buf 0
    {
        const __half* ksrc = kb0 + (size_t)crow0 * DH + cc8;
        const __half* vsrc = vb0 + (size_t)crow0 * DH + cc8;
        cpasync16(ks0 + cdst, ksrc);
        cpasync16(vs0 + cdst, vsrc);
        cpasync16(ks0 + cdst + 32 * 144, ksrc + 32 * DH);
        cpasync16(vs0 + cdst + 32 * 144, vsrc + 32 * DH);
        asm volatile("cp.async.commit_group;");
    }

    for (int i = tid; i < T_; i += 256) Mall[i] = mask[b * T_ + i];

    // Q fragments (already scaled by 0.125*log2e at QKV epilogue)
    unsigned qf[4][4];
    {
        const __half* qb = Qh + ((size_t)bh * T_ + mrow0) * DH;
#pragma unroll
        for (int kt = 0; kt < 4; kt++) {
            qf[kt][0] = *(const unsigned*)(qb + (size_t)g       * DH + kt*16 + 2*l);
            qf[kt][1] = *(const unsigned*)(qb + (size_t)(g + 8) * DH + kt*16 + 2*l);
            qf[kt][2] = *(const unsigned*)(qb + (size_t)g       * DH + kt*16 + 2*l + 8);
            qf[kt][3] = *(const unsigned*)(qb + (size_t)(g + 8) * DH + kt*16 + 2*l + 8);
        }
    }

    float oa[8][4];
#pragma unroll
    for (int ni = 0; ni < 8; ni++)
#pragma unroll
        for (int e = 0; e < 4; e++) oa[ni][e] = 0.0f;
    float m0 = -INFINITY, m1 = -INFINITY;
    float l0 = 0.0f, l1 = 0.0f;

    const int sbq_base = ((lane & 7) * KPW + ((lane >> 3) & 1) * 4) * 4;
    const int pvb_base = ((lane & 15) * KPW) * 4;

    for (int t = 0; t < 32; t++) {
        const int buf = t & 1;
        asm volatile("cp.async.wait_group 0;");
        __syncthreads();

        // issue next tile into the other buffer
        if (t < 31) {
            const int nb = buf ^ 1;
            const __half* ksrc = kb0 + (size_t)((t + 1) * FBN + crow0) * DH + cc8;
            const __half* vsrc = vb0 + (size_t)((t + 1) * FBN + crow0) * DH + cc8;
            cpasync16(ks0 + nb * ATB + cdst, ksrc);
            cpasync16(vs0 + nb * ATB + cdst, vsrc);
            cpasync16(ks0 + nb * ATB + cdst + 32 * 144, ksrc + 32 * DH);
            cpasync16(vs0 + nb * ATB + cdst + 32 * 144, vsrc + 32 * DH);
            asm volatile("cp.async.commit_group;");
        }

        // S = Q K^T
        float sa[8][4];
#pragma unroll
        for (int ni = 0; ni < 8; ni++)
#pragma unroll
            for (int e = 0; e < 4; e++) sa[ni][e] = 0.0f;
        const uint32_t kbase = ks0 + buf * ATB;
#pragma unroll
        for (int kt = 0; kt < 4; kt++) {
#pragma unroll
            for (int ni = 0; ni < 8; ni++) {
                unsigned bq[2];
                ldsm_x2(bq, kbase + sbq_base + ni * 1152 + kt * 32);
                mma_f16(sa[ni], qf[kt], bq);
            }
        }

        // mask (scores already in log2 domain)
        const int mb = t * FBN;
#pragma unroll
        for (int ni = 0; ni < 8; ni++) {
            int c0m = Mall[mb + ni*8 + 2*l];
            int c1m = Mall[mb + ni*8 + 2*l + 1];
            if (!c0m) { sa[ni][0] = NEG_INF_F; sa[ni][2] = NEG_INF_F; }
            if (!c1m) { sa[ni][1] = NEG_INF_F; sa[ni][3] = NEG_INF_F; }
        }

        float rm0 = -INFINITY, rm1 = -INFINITY;
#pragma unroll
        for (int ni = 0; ni < 8; ni++) {
            rm0 = fmaxf(rm0, fmaxf(sa[ni][0], sa[ni][1]));
            rm1 = fmaxf(rm1, fmaxf(sa[ni][2], sa[ni][3]));
        }
        rm0 = fmaxf(rm0, __shfl_xor_sync(0xffffffffu, rm0, 1));
        rm0 = fmaxf(rm0, __shfl_xor_sync(0xffffffffu, rm0, 2));
        rm1 = fmaxf(rm1, __shfl_xor_sync(0xffffffffu, rm1, 1));
        rm1 = fmaxf(rm1, __shfl_xor_sync(0xffffffffu, rm1, 2));
        float mn0 = fmaxf(m0, rm0);
        float mn1 = fmaxf(m1, rm1);
        float cr0 = ex2(m0 - mn0);
        float cr1 = ex2(m1 - mn1);

        unsigned pk[8][2];
        float ts0 = 0.0f, ts1 = 0.0f;
#pragma unroll
        for (int ni = 0; ni < 8; ni++) {
            float e0 = ex2(sa[ni][0] - mn0);
            float e1 = ex2(sa[ni][1] - mn0);
            float e2 = ex2(sa[ni][2] - mn1);
            float e3 = ex2(sa[ni][3] - mn1);
            ts0 += e0 + e1;
            ts1 += e2 + e3;
            pk[ni][0] = packh2(e0, e1);
            pk[ni][1] = packh2(e2, e3);
        }
        l0 = l0 * cr0 + ts0;
        l1 = l1 * cr1 + ts1;
#pragma unroll
        for (int ni = 0; ni < 8; ni++) {
            oa[ni][0] *= cr0; oa[ni][1] *= cr0;
            oa[ni][2] *= cr1; oa[ni][3] *= cr1;
        }
        m0 = mn0; m1 = mn1;

        // O += P V  (V b-frags via ldmatrix.trans on row-major tile)
        const uint32_t vbase = vs0 + buf * ATB;
#pragma unroll
        for (int kt2 = 0; kt2 < 4; kt2++) {
            unsigned pa[4];
            pa[0] = pk[2*kt2][0];
            pa[1] = pk[2*kt2][1];
            pa[2] = pk[2*kt2 + 1][0];
            pa[3] = pk[2*kt2 + 1][1];
#pragma unroll
            for (int ni = 0; ni < 8; ni++) {
                unsigned bv[2];
                ldsm_x2t(bv, vbase + pvb_base + kt2 * 2304 + ni * 16);
                mma_f16(oa[ni], pa, bv);
            }
        }
    }

    l0 += __shfl_xor_sync(0xffffffffu, l0, 1);
    l0 += __shfl_xor_sync(0xffffffffu, l0, 2);
    l1 += __shfl_xor_sync(0xffffffffu, l1, 1);
    l1 += __shfl_xor_sync(0xffffffffu, l1, 2);
    float i0 = 1.0f / l0;
    float i1 = 1.0f / l1;

    __half* ob = O + ((size_t)(b * T_ + mrow0)) * D_ + h * DH;
#pragma unroll
    for (int ni = 0; ni < 8; ni++) {
        unsigned v0 = packh2(oa[ni][0] * i0, oa[ni][1] * i0);
        unsigned v1 = packh2(oa[ni][2] * i1, oa[ni][3] * i1);
        *(unsigned*)(ob + (size_t)g       * D_ + ni*8 + 2*l) = v0;
        *(unsigned*)(ob + (size_t)(g + 8) * D_ + ni*8 + 2*l) = v1;
    }
}

// ===========================================================================
extern "C" void kernel_launch(void* const* d_in, const int* in_sizes, int n_in,
                              void* d_out, int out_size)
{
    (void)in_sizes; (void)n_in; (void)out_size;
    const float* x    = (const float*)d_in[0];
    const int*   mask = (const int*)  d_in[1];
    const float* Wq   = (const float*)d_in[2];
    const float* bq   = (const float*)d_in[3];
    const float* Wk   = (const float*)d_in[4];
    const float* bk   = (const float*)d_in[5];
    const float* Wv   = (const float*)d_in[6];
    const float* bv   = (const float*)d_in[7];
    const float* Wo   = (const float*)d_in[8];
    const float* bo   = (const float*)d_in[9];
    float* out = (float*)d_out;

    __half *q, *k, *v, *attn, *xh, *wh;
    cudaGetSymbolAddress((void**)&q,    g_qh);
    cudaGetSymbolAddress((void**)&k,    g_kh);
    cudaGetSymbolAddress((void**)&v,    g_vh);
    cudaGetSymbolAddress((void**)&attn, g_attn);
    cudaGetSymbolAddress((void**)&xh,   g_xh);
    cudaGetSymbolAddress((void**)&wh,   g_wh);

    // convert x + all weights to fp16 (2M float4 units)
    convert_all<<<8192, 256>>>(x, Wq, Wk, Wv, Wo, xh, wh);

    // fused QKV projections (fp16 out, q pre-scaled by 0.125*log2e)
    mma_gemm_f16<<<dim3(D_/128, M_/128, 3), 256>>>(
        xh, wh, bq, q, bk, k, bv, v, 1, QSC);

    attn_f16<<<dim3(T_/FBM, B_*H_), 256>>>(q, k, v, mask, attn);

    // output projection (fp32 out); W = wh + 3*2^20
    mma_gemm_f16<<<dim3(D_/128, M_/128, 1), 256>>>(
        attn, wh + ((size_t)3 << 20), bo, out, bo, out, bo, out, 0, 1.0f);
}

// round 10
// speedup vs baseline: 8.6386x; 1.0846x over previous
#include <cuda_runtime.h>
#include <cuda_fp16.h>
#include <cstdint>
#include <math.h>

#define B_  2
#define T_  2048
#define D_  1024
#define H_  16
#define DH  64
#define M_  (B_*T_)
#define NEG_INF_F (-1.0e9f)
#define QSC 0.18033688011112042f   // 0.125 * log2(e)

// Scratch (allocation-free rule: __device__ globals)
__device__ __half g_qh[(size_t)B_*H_*T_*DH];
__device__ __half g_kh[(size_t)B_*H_*T_*DH];
__device__ __half g_vh[(size_t)B_*H_*T_*DH];
__device__ __half g_attn[(size_t)M_*D_];
__device__ __half g_xh[(size_t)M_*D_];
__device__ __half g_wh[(size_t)4*D_*D_];

// ===========================================================================
// helpers
// ===========================================================================
__device__ __forceinline__ unsigned packh2(float lo, float hi) {
    __half2 h = __floats2half2_rn(lo, hi);
    return *(unsigned*)&h;
}
__device__ __forceinline__ float ex2(float x) {
    float y;
    asm("ex2.approx.ftz.f32 %0, %1;" : "=f"(y) : "f"(x));
    return y;
}
__device__ __forceinline__ uint32_t smaddr(const void* p) {
    return (uint32_t)__cvta_generic_to_shared(p);
}
__device__ __forceinline__ void mma_f16(float* c, const unsigned* a, const unsigned* b) {
    asm volatile(
        "mma.sync.aligned.m16n8k16.row.col.f32.f16.f16.f32 "
        "{%0,%1,%2,%3}, {%4,%5,%6,%7}, {%8,%9}, {%0,%1,%2,%3};\n"
        : "+f"(c[0]), "+f"(c[1]), "+f"(c[2]), "+f"(c[3])
        : "r"(a[0]), "r"(a[1]), "r"(a[2]), "r"(a[3]),
          "r"(b[0]), "r"(b[1]));
}
__device__ __forceinline__ void ldsm_x4(unsigned* r, uint32_t a) {
    asm volatile("ldmatrix.sync.aligned.m8n8.x4.shared.b16 {%0,%1,%2,%3}, [%4];"
        : "=r"(r[0]), "=r"(r[1]), "=r"(r[2]), "=r"(r[3]) : "r"(a));
}
__device__ __forceinline__ void ldsm_x2(unsigned* r, uint32_t a) {
    asm volatile("ldmatrix.sync.aligned.m8n8.x2.shared.b16 {%0,%1}, [%2];"
        : "=r"(r[0]), "=r"(r[1]) : "r"(a));
}
__device__ __forceinline__ void ldsm_x2t(unsigned* r, uint32_t a) {
    asm volatile("ldmatrix.sync.aligned.m8n8.x2.trans.shared.b16 {%0,%1}, [%2];"
        : "=r"(r[0]), "=r"(r[1]) : "r"(a));
}
__device__ __forceinline__ void cpasync16(uint32_t dst, const void* src) {
    asm volatile("cp.async.cg.shared.global [%0], [%1], 16;" :: "r"(dst), "l"(src));
}

// ===========================================================================
// fp32 -> fp16 conversion for x (1M float4) and 4 weight matrices (256K each)
// ===========================================================================
__global__ __launch_bounds__(256) void convert_all(
    const float* __restrict__ x,
    const float* __restrict__ wq, const float* __restrict__ wk,
    const float* __restrict__ wv, const float* __restrict__ wo,
    __half* __restrict__ xh, __half* __restrict__ wh)
{
    const int idx = blockIdx.x * 256 + threadIdx.x;   // 0 .. 2M-1 (float4 units)
    const float* src;
    __half* dst;
    if (idx < (1 << 20)) {
        src = x + (size_t)idx * 4;
        dst = xh + (size_t)idx * 4;
    } else {
        int j = idx - (1 << 20);
        int w = j >> 18;
        int off = j & ((1 << 18) - 1);
        const float* ws = (w == 0) ? wq : (w == 1) ? wk : (w == 2) ? wv : wo;
        src = ws + (size_t)off * 4;
        dst = wh + ((size_t)w << 20) + (size_t)off * 4;
    }
    float4 v = *(const float4*)src;
    uint2 u;
    u.x = packh2(v.x, v.y);
    u.y = packh2(v.z, v.w);
    *(uint2*)dst = u;
}

// ===========================================================================
// fp16 tensor-core GEMM: C = A[M,1024] @ W[1024,1024]^T + bias
// 128x128 tile, BK=32, 3-stage cp.async pipeline in 48KB static smem.
// Swizzled 64B rows (chunk ^= (row>>1)&3) -> conflict-free, no padding.
// ONE __syncthreads per K-tile. 256 threads, 2 CTAs/SM.
// mode 0: fp32 C[m*1024+n].  mode 1: fp16 qkv layout [B,H,T,dh], z=0 scaled.
// ===========================================================================
#define GBUF 8192            // 128 rows * 64 B
#define GSTG3 3

__global__ __launch_bounds__(256, 2) void mma_gemm_f16(
    const __half* __restrict__ A, const __half* __restrict__ Wbase,
    const float* __restrict__ bb0, void* __restrict__ C0,
    const float* __restrict__ bb1, void* __restrict__ C1,
    const float* __restrict__ bb2, void* __restrict__ C2,
    int mode, float scale0)
{
    const int z = blockIdx.z;
    const __half* W   = Wbase + ((size_t)z << 20);
    const float* bias = (z == 0) ? bb0 : (z == 1) ? bb1 : bb2;
    void* C           = (z == 0) ? C0  : (z == 1) ? C1  : C2;
    const float sc    = (z == 0) ? scale0 : 1.0f;

    __shared__ unsigned char gsm[2 * GSTG3 * GBUF];   // 49152 = 48 KB exactly

    const int tid  = threadIdx.x;
    const int warp = tid >> 5, lane = tid & 31;
    const int g = lane >> 2, l = lane & 3;
    const int wm = (warp >> 2) * 64;
    const int wn = (warp & 3) * 32;
    const int m0 = blockIdx.y * 128;
    const int n0 = blockIdx.x * 128;

    // cp.async mapping: rows crow, crow+64; chunk c16 = tid&3 (16B units)
    const int crow = tid >> 2;                      // 0..63
    const int cch  = (tid & 3) * 8;                 // half offset in 32-half row
    const int sst  = (tid >> 3) & 3;                // store swizzle = (crow>>1)&3
    const int cdst = crow * 64 + (((tid & 3) ^ sst) * 16);

    // ldmatrix addressing (swizzle term independent of mi/ni since warp-tile
    // row offsets are multiples of 8 rows)
    const int a_hi  = lane >> 4;
    const int sa    = ((lane & 15) >> 1) & 3;
    const int a_row = (wm + (lane & 15)) * 64;
    const int ac0   = ((0 + a_hi) ^ sa) * 16;       // kk=0 chunk offsets
    const int ac1   = ((2 + a_hi) ^ sa) * 16;       // kk=1
    const int b_hi  = (lane >> 3) & 1;
    const int sb    = ((lane & 7) >> 1) & 3;
    const int b_row = (wn + (lane & 7)) * 64;
    const int bc0   = ((0 + b_hi) ^ sb) * 16;
    const int bc1   = ((2 + b_hi) ^ sb) * 16;

    const uint32_t sA0 = smaddr(gsm);
    const uint32_t sW0 = sA0 + GSTG3 * GBUF;

    const __half* Abase = A + (size_t)(m0 + crow) * D_ + cch;
    const __half* Wrow  = W + (size_t)(n0 + crow) * D_ + cch;

    float acc[4][4][4];
#pragma unroll
    for (int mi = 0; mi < 4; mi++)
#pragma unroll
        for (int ni = 0; ni < 4; ni++)
#pragma unroll
            for (int e = 0; e < 4; e++) acc[mi][ni][e] = 0.0f;

    // prologue: tiles 0 and 1 -> bufs 0,1
#pragma unroll
    for (int s = 0; s < 2; s++) {
        const __half* as = Abase + s * 32;
        const __half* ws = Wrow  + s * 32;
        cpasync16(sA0 + s * GBUF + cdst, as);
        cpasync16(sW0 + s * GBUF + cdst, ws);
        cpasync16(sA0 + s * GBUF + cdst + 4096, as + 64 * D_);
        cpasync16(sW0 + s * GBUF + cdst + 4096, ws + 64 * D_);
        asm volatile("cp.async.commit_group;");
    }

    int bc = 0;      // kt % 3
    int nb = 2;      // (kt+2) % 3
    for (int kt = 0; kt < 32; kt++) {
        asm volatile("cp.async.wait_group 1;");
        __syncthreads();

        // issue tile kt+2 (clamped; dup tail loads land in finished buffers)
        {
            const int nt = (kt + 2 < 32) ? (kt + 2) : 31;
            const __half* as = Abase + nt * 32;
            const __half* ws = Wrow  + nt * 32;
            cpasync16(sA0 + nb * GBUF + cdst, as);
            cpasync16(sW0 + nb * GBUF + cdst, ws);
            cpasync16(sA0 + nb * GBUF + cdst + 4096, as + 64 * D_);
            cpasync16(sW0 + nb * GBUF + cdst + 4096, ws + 64 * D_);
            asm volatile("cp.async.commit_group;");
        }

        const uint32_t aB = sA0 + bc * GBUF + a_row;
        const uint32_t bB = sW0 + bc * GBUF + b_row;
#pragma unroll
        for (int kk = 0; kk < 2; kk++) {
            const int aco = kk ? ac1 : ac0;
            const int bco = kk ? bc1 : bc0;
            unsigned af[4][4], bf[4][2];
#pragma unroll
            for (int mi = 0; mi < 4; mi++)
                ldsm_x4(af[mi], aB + mi * 1024 + aco);
#pragma unroll
            for (int ni = 0; ni < 4; ni++)
                ldsm_x2(bf[ni], bB + ni * 512 + bco);
#pragma unroll
            for (int mi = 0; mi < 4; mi++)
#pragma unroll
                for (int ni = 0; ni < 4; ni++)
                    mma_f16(acc[mi][ni], af[mi], bf[ni]);
        }

        bc++; if (bc == 3) bc = 0;
        nb++; if (nb == 3) nb = 0;
    }

    // epilogue
#pragma unroll
    for (int ni = 0; ni < 4; ni++) {
        int n = n0 + wn + ni * 8 + 2 * l;
        float bv0 = __ldg(bias + n);
        float bv1 = __ldg(bias + n + 1);
#pragma unroll
        for (int mi = 0; mi < 4; mi++) {
            int m = m0 + wm + mi * 16 + g;
#pragma unroll
            for (int half_ = 0; half_ < 2; half_++) {
                int mm = m + half_ * 8;
                float v0 = acc[mi][ni][half_ * 2 + 0] + bv0;
                float v1 = acc[mi][ni][half_ * 2 + 1] + bv1;
                if (mode == 0) {
                    float2 v; v.x = v0; v.y = v1;
                    *(float2*)((float*)C + (size_t)mm * D_ + n) = v;
                } else {
                    int bb = mm >> 11;
                    int t  = mm & (T_ - 1);
                    int hh = n >> 6;
                    int d  = n & (DH - 1);
                    unsigned hv = packh2(v0 * sc, v1 * sc);
                    *(unsigned*)((__half*)C + (((size_t)(bb * H_ + hh)) * T_ + t) * DH + d) = hv;
                }
            }
        }
    }
}

// ===========================================================================
// fp16 flash attention: BM=256 (16 warps, 512 threads), BN=64, dh=64.
// Halves per-head K/V L2 traffic vs BM=128. 2-stage cp.async pipeline,
// ONE __syncthreads per tile. V via ldmatrix.trans. Output fp16 [B,T,D].
// ===========================================================================
#define FBM 256
#define FBN 64
#define KPW 36            // smem word pitch (72 halves)
#define ATB (FBN*72*2)    // bytes per K (or V) buffer = 9216

__global__ __launch_bounds__(512, 1) void attn_f16(
    const __half* __restrict__ Qh, const __half* __restrict__ Kh,
    const __half* __restrict__ Vh, const int* __restrict__ mask,
    __half* __restrict__ O)
{
    __shared__ __half Ks[2][FBN][72];
    __shared__ __half Vs[2][FBN][72];
    __shared__ int    Mall[T_];

    const int bh = blockIdx.y;
    const int b  = bh >> 4;
    const int h  = bh & (H_ - 1);
    const int tid  = threadIdx.x;
    const int warp = tid >> 5, lane = tid & 31;
    const int g = lane >> 2, l = lane & 3;
    const int mrow0 = blockIdx.x * FBM + warp * 16;

    const __half* kb0 = Kh + (size_t)bh * T_ * DH;
    const __half* vb0 = Vh + (size_t)bh * T_ * DH;
    const uint32_t ks0 = smaddr(&Ks[0][0][0]);
    const uint32_t vs0 = smaddr(&Vs[0][0][0]);

    // tile-load mapping: 512 threads, 1 x 16B chunk per tensor each
    const int crow0 = tid >> 3;          // 0..63
    const int cc8   = (tid & 7) * 8;     // half col
    const int cdst  = crow0 * 144 + (tid & 7) * 16;

    // prologue: tile 0 -> buf 0
    {
        cpasync16(ks0 + cdst, kb0 + (size_t)crow0 * DH + cc8);
        cpasync16(vs0 + cdst, vb0 + (size_t)crow0 * DH + cc8);
        asm volatile("cp.async.commit_group;");
    }

    for (int i = tid; i < T_; i += 512) Mall[i] = mask[b * T_ + i];

    // Q fragments (already scaled by 0.125*log2e at QKV epilogue)
    unsigned qf[4][4];
    {
        const __half* qb = Qh + ((size_t)bh * T_ + mrow0) * DH;
#pragma unroll
        for (int kt = 0; kt < 4; kt++) {
            qf[kt][0] = *(const unsigned*)(qb + (size_t)g       * DH + kt*16 + 2*l);
            qf[kt][1] = *(const unsigned*)(qb + (size_t)(g + 8) * DH + kt*16 + 2*l);
            qf[kt][2] = *(const unsigned*)(qb + (size_t)g       * DH + kt*16 + 2*l + 8);
            qf[kt][3] = *(const unsigned*)(qb + (size_t)(g + 8) * DH + kt*16 + 2*l + 8);
        }
    }

    float oa[8][4];
#pragma unroll
    for (int ni = 0; ni < 8; ni++)
#pragma unroll
        for (int e = 0; e < 4; e++) oa[ni][e] = 0.0f;
    float m0 = -INFINITY, m1 = -INFINITY;
    float l0 = 0.0f, l1 = 0.0f;

    const int sbq_base = ((lane & 7) * KPW + ((lane >> 3) & 1) * 4) * 4;
    const int pvb_base = ((lane & 15) * KPW) * 4;

    for (int t = 0; t < 32; t++) {
        const int buf = t & 1;
        asm volatile("cp.async.wait_group 0;");
        __syncthreads();

        // issue next tile into the other buffer
        if (t < 31) {
            const int nb2 = buf ^ 1;
            cpasync16(ks0 + nb2 * ATB + cdst, kb0 + (size_t)((t + 1) * FBN + crow0) * DH + cc8);
            cpasync16(vs0 + nb2 * ATB + cdst, vb0 + (size_t)((t + 1) * FBN + crow0) * DH + cc8);
            asm volatile("cp.async.commit_group;");
        }

        // S = Q K^T
        float sa[8][4];
#pragma unroll
        for (int ni = 0; ni < 8; ni++)
#pragma unroll
            for (int e = 0; e < 4; e++) sa[ni][e] = 0.0f;
        const uint32_t kbase = ks0 + buf * ATB;
#pragma unroll
        for (int kt = 0; kt < 4; kt++) {
#pragma unroll
            for (int ni = 0; ni < 8; ni++) {
                unsigned bq[2];
                ldsm_x2(bq, kbase + sbq_base + ni * 1152 + kt * 32);
                mma_f16(sa[ni], qf[kt], bq);
            }
        }

        // mask (scores already in log2 domain)
        const int mb = t * FBN;
#pragma unroll
        for (int ni = 0; ni < 8; ni++) {
            int c0m = Mall[mb + ni*8 + 2*l];
            int c1m = Mall[mb + ni*8 + 2*l + 1];
            if (!c0m) { sa[ni][0] = NEG_INF_F; sa[ni][2] = NEG_INF_F; }
            if (!c1m) { sa[ni][1] = NEG_INF_F; sa[ni][3] = NEG_INF_F; }
        }

        float rm0 = -INFINITY, rm1 = -INFINITY;
#pragma unroll
        for (int ni = 0; ni < 8; ni++) {
            rm0 = fmaxf(rm0, fmaxf(sa[ni][0], sa[ni][1]));
            rm1 = fmaxf(rm1, fmaxf(sa[ni][2], sa[ni][3]));
        }
        rm0 = fmaxf(rm0, __shfl_xor_sync(0xffffffffu, rm0, 1));
        rm0 = fmaxf(rm0, __shfl_xor_sync(0xffffffffu, rm0, 2));
        rm1 = fmaxf(rm1, __shfl_xor_sync(0xffffffffu, rm1, 1));
        rm1 = fmaxf(rm1, __shfl_xor_sync(0xffffffffu, rm1, 2));
        float mn0 = fmaxf(m0, rm0);
        float mn1 = fmaxf(m1, rm1);
        float cr0 = ex2(m0 - mn0);
        float cr1 = ex2(m1 - mn1);

        unsigned pk[8][2];
        float ts0 = 0.0f, ts1 = 0.0f;
#pragma unroll
        for (int ni = 0; ni < 8; ni++) {
            float e0 = ex2(sa[ni][0] - mn0);
            float e1 = ex2(sa[ni][1] - mn0);
            float e2 = ex2(sa[ni][2] - mn1);
            float e3 = ex2(sa[ni][3] - mn1);
            ts0 += e0 + e1;
            ts1 += e2 + e3;
            pk[ni][0] = packh2(e0, e1);
            pk[ni][1] = packh2(e2, e3);
        }
        l0 = l0 * cr0 + ts0;
        l1 = l1 * cr1 + ts1;
#pragma unroll
        for (int ni = 0; ni < 8; ni++) {
            oa[ni][0] *= cr0; oa[ni][1] *= cr0;
            oa[ni][2] *= cr1; oa[ni][3] *= cr1;
        }
        m0 = mn0; m1 = mn1;

        // O += P V  (V b-frags via ldmatrix.trans on row-major tile)
        const uint32_t vbase = vs0 + buf * ATB;
#pragma unroll
        for (int kt2 = 0; kt2 < 4; kt2++) {
            unsigned pa[4];
            pa[0] = pk[2*kt2][0];
            pa[1] = pk[2*kt2][1];
            pa[2] = pk[2*kt2 + 1][0];
            pa[3] = pk[2*kt2 + 1][1];
#pragma unroll
            for (int ni = 0; ni < 8; ni++) {
                unsigned bv[2];
                ldsm_x2t(bv, vbase + pvb_base + kt2 * 2304 + ni * 16);
                mma_f16(oa[ni], pa, bv);
            }
        }
    }

    l0 += __shfl_xor_sync(0xffffffffu, l0, 1);
    l0 += __shfl_xor_sync(0xffffffffu, l0, 2);
    l1 += __shfl_xor_sync(0xffffffffu, l1, 1);
    l1 += __shfl_xor_sync(0xffffffffu, l1, 2);
    float i0 = 1.0f / l0;
    float i1 = 1.0f / l1;

    __half* ob = O + ((size_t)(b * T_ + mrow0)) * D_ + h * DH;
#pragma unroll
    for (int ni = 0; ni < 8; ni++) {
        unsigned v0 = packh2(oa[ni][0] * i0, oa[ni][1] * i0);
        unsigned v1 = packh2(oa[ni][2] * i1, oa[ni][3] * i1);
        *(unsigned*)(ob + (size_t)g       * D_ + ni*8 + 2*l) = v0;
        *(unsigned*)(ob + (size_t)(g + 8) * D_ + ni*8 + 2*l) = v1;
    }
}

// ===========================================================================
extern "C" void kernel_launch(void* const* d_in, const int* in_sizes, int n_in,
                              void* d_out, int out_size)
{
    (void)in_sizes; (void)n_in; (void)out_size;
    const float* x    = (const float*)d_in[0];
    const int*   mask = (const int*)  d_in[1];
    const float* Wq   = (const float*)d_in[2];
    const float* bq   = (const float*)d_in[3];
    const float* Wk   = (const float*)d_in[4];
    const float* bk   = (const float*)d_in[5];
    const float* Wv   = (const float*)d_in[6];
    const float* bv   = (const float*)d_in[7];
    const float* Wo   = (const float*)d_in[8];
    const float* bo   = (const float*)d_in[9];
    float* out = (float*)d_out;

    __half *q, *k, *v, *attn, *xh, *wh;
    cudaGetSymbolAddress((void**)&q,    g_qh);
    cudaGetSymbolAddress((void**)&k,    g_kh);
    cudaGetSymbolAddress((void**)&v,    g_vh);
    cudaGetSymbolAddress((void**)&attn, g_attn);
    cudaGetSymbolAddress((void**)&xh,   g_xh);
    cudaGetSymbolAddress((void**)&wh,   g_wh);

    // convert x + all weights to fp16 (2M float4 units)
    convert_all<<<8192, 256>>>(x, Wq, Wk, Wv, Wo, xh, wh);

    // fused QKV projections (fp16 out, q pre-scaled by 0.125*log2e)
    mma_gemm_f16<<<dim3(D_/128, M_/128, 3), 256>>>(
        xh, wh, bq, q, bk, k, bv, v, 1, QSC);

    attn_f16<<<dim3(T_/FBM, B_*H_), 512>>>(q, k, v, mask, attn);

    // output projection (fp32 out); W = wh + 3*2^20
    mma_gemm_f16<<<dim3(D_/128, M_/128, 1), 256>>>(
        attn, wh + ((size_t)3 << 20), bo, out, bo, out, bo, out, 0, 1.0f);
}